// round 12
// baseline (speedup 1.0000x reference)
#include <cuda_runtime.h>
#include <cuda_fp16.h>
#include <stdint.h>
#include <math.h>

#define B_   2
#define T_   1024
#define D_   6144
#define NQ_  48
#define NKV_ 8
#define HD_  128
#define GRP_ 6
#define KVD_ 1024
#define MULT_ 0.08838834764831845f
#define CK_  0.0085011611f          /* MULT * log2(e) / 15 */
#define L2E_ 1.4426950408889634f

#define NK_   (D_ / 32)
#define ROWB  80
#define O_AH  0
#define O_AL  10240
#define O_B   20480
#define STG   30720
#define SMEM_TOT (3 * STG)

/* attention smem */
#define AT_KH 0
#define AT_KL 8704
#define AT_VT 17408
#define AT_STG 28288
#define AT_SMEM (2 * AT_STG)

// ---------------- scratch ----------------
__device__ __align__(128) float g_Q[(size_t)B_ * T_ * D_];
__device__ __align__(128) float g_K[(size_t)B_ * T_ * KVD_];
__device__ __align__(128) float g_V[(size_t)B_ * T_ * KVD_];
__device__ __align__(16) __half g_Ah[(size_t)B_ * T_ * D_];
__device__ __align__(16) __half g_Al[(size_t)B_ * T_ * D_];
__device__ __align__(16) __half g_Kh[(size_t)B_ * NKV_ * T_ * HD_];
__device__ __align__(16) __half g_Kl[(size_t)B_ * NKV_ * T_ * HD_];
__device__ __align__(16) __half g_VT[(size_t)B_ * NKV_ * 136 * T_];
__device__ __align__(16) __half g_Wq[(size_t)D_ * D_];
__device__ __align__(16) __half g_Wk[(size_t)KVD_ * D_];
__device__ __align__(16) __half g_Wv[(size_t)KVD_ * D_];
__device__ __align__(16) __half g_Wo[(size_t)D_ * D_];
__device__ float2 g_trig[T_ * 64];

// ---------------- ptx helpers ----------------
__device__ __forceinline__ uint32_t smem_u32(const void* p) {
    uint32_t a;
    asm("{ .reg .u64 t; cvta.to.shared.u64 t, %1; cvt.u32.u64 %0, t; }" : "=r"(a) : "l"(p));
    return a;
}
__device__ __forceinline__ void cp16(uint32_t d, const void* s) {
    asm volatile("cp.async.cg.shared.global [%0], [%1], 16;" :: "r"(d), "l"(s));
}
#define CP_COMMIT() asm volatile("cp.async.commit_group;" ::: "memory")
#define LDSM4(r0, r1, r2, r3, a) \
    asm volatile("ldmatrix.sync.aligned.m8n8.x4.shared.b16 {%0,%1,%2,%3}, [%4];" \
                 : "=r"(r0), "=r"(r1), "=r"(r2), "=r"(r3) : "r"(a))
#define LDSM2(r0, r1, a) \
    asm volatile("ldmatrix.sync.aligned.m8n8.x2.shared.b16 {%0,%1}, [%2];" \
                 : "=r"(r0), "=r"(r1) : "r"(a))
__device__ __forceinline__ void mma16816(float* c, const uint32_t* a, const uint32_t* b) {
    asm volatile(
        "mma.sync.aligned.m16n8k16.row.col.f32.f16.f16.f32 "
        "{%0,%1,%2,%3}, {%4,%5,%6,%7}, {%8,%9}, {%0,%1,%2,%3};"
        : "+f"(c[0]), "+f"(c[1]), "+f"(c[2]), "+f"(c[3])
        : "r"(a[0]), "r"(a[1]), "r"(a[2]), "r"(a[3]), "r"(b[0]), "r"(b[1]));
}
__device__ __forceinline__ uint32_t packh2(float x, float y) {
    __half2 h = __floats2half2_rn(x, y);
    return *(uint32_t*)&h;
}
__device__ __forceinline__ float ex2f(float x) {
    float r; asm("ex2.approx.f32 %0, %1;" : "=f"(r) : "f"(x)); return r;
}
__device__ __forceinline__ float rcpf(float x) {
    float r; asm("rcp.approx.f32 %0, %1;" : "=f"(r) : "f"(x)); return r;
}

// ---------------- prep kernels ----------------
__global__ __launch_bounds__(256) void wT_fp16(
    const float* __restrict__ W, __half* __restrict__ Tr, int K, int N)
{
    __shared__ float tb[32][33];
    const int n0 = blockIdx.x * 32, k0 = blockIdx.y * 32;
    const int tx = threadIdx.x, ty = threadIdx.y;
#pragma unroll
    for (int j = 0; j < 4; ++j)
        tb[ty + j * 8][tx] = W[(size_t)(k0 + ty + j * 8) * N + n0 + tx];
    __syncthreads();
#pragma unroll
    for (int j = 0; j < 4; ++j) {
        int n = ty + j * 8;
        Tr[(size_t)(n0 + n) * K + k0 + tx] = __float2half_rn(tb[tx][n]);
    }
}

__global__ __launch_bounds__(256) void split_fp16(
    const float* __restrict__ X, __half* __restrict__ H,
    __half* __restrict__ L, int n4)
{
    int i = blockIdx.x * 256 + threadIdx.x;
    if (i >= n4) return;
    float4 v = ((const float4*)X)[i];
    ushort4 hh, ll;
    float f[4] = {v.x, v.y, v.z, v.w};
    unsigned short* hp = &hh.x; unsigned short* lp = &ll.x;
#pragma unroll
    for (int k = 0; k < 4; ++k) {
        __half h = __float2half_rn(f[k]);
        __half l = __float2half_rn(f[k] - __half2float(h));
        hp[k] = __half_as_ushort(h); lp[k] = __half_as_ushort(l);
    }
    ((ushort4*)H)[i] = hh; ((ushort4*)L)[i] = ll;
}

__global__ __launch_bounds__(256) void kvsplit(const float* __restrict__ K)
{
    int i = blockIdx.x * 256 + threadIdx.x;
    int d4 = i & 31, t = (i >> 5) & (T_ - 1), kvb = i >> 15;
    int b = kvb >> 3, kv = kvb & 7;
    float4 v = *(const float4*)(K + ((size_t)(b * T_ + t) * KVD_ + kv * 128 + d4 * 4));
    ushort4 hh, ll;
    float f[4] = {v.x, v.y, v.z, v.w};
    unsigned short* hp = &hh.x; unsigned short* lp = &ll.x;
#pragma unroll
    for (int k = 0; k < 4; ++k) {
        __half h = __float2half_rn(f[k]);
        __half l = __float2half_rn(f[k] - __half2float(h));
        hp[k] = __half_as_ushort(h); lp[k] = __half_as_ushort(l);
    }
    size_t o = ((size_t)kvb * T_ + t) * 128 + d4 * 4;
    *(ushort4*)(g_Kh + o) = hh; *(ushort4*)(g_Kl + o) = ll;
}

__global__ __launch_bounds__(256) void vtsplit(const float* __restrict__ V)
{
    int i = blockIdx.x * 256 + threadIdx.x;
    if (i >= 16 * 136 * 256) return;
    int t4 = i & 255, n = (i >> 8) % 136, kvb = i / (136 * 256);
    int b = kvb >> 3, kv = kvb & 7;
    ushort4 o;
    unsigned short* op = &o.x;
    int t = t4 * 4;
#pragma unroll
    for (int j = 0; j < 4; ++j) {
        float x = (n < 128) ? V[(size_t)(b * T_ + t + j) * KVD_ + kv * 128 + n]
                            : (n == 128 ? 1.0f : 0.0f);
        op[j] = __half_as_ushort(__float2half_rn(x));
    }
    *(ushort4*)(g_VT + ((size_t)kvb * 136 + n) * T_ + t) = o;
}

// ---------------- HMMA fp16x2 GEMM: 128x128 CTA, 4 warps, 64x64 warp tile -
__global__ __launch_bounds__(128, 2) void gemm_mma(
    const __half* __restrict__ Ahp, const __half* __restrict__ Alp,
    const __half* __restrict__ Bp,
    const float* __restrict__ bias, float* __restrict__ C, int N)
{
    extern __shared__ char smraw[];
    const uint32_t sb = smem_u32(smraw);
    const int tid = threadIdx.x, wid = tid >> 5, lane = tid & 31;
    const int wm = wid & 1, wn = wid >> 1;        // 2x2 warp grid, 64x64 tiles
    const size_t row0 = (size_t)blockIdx.x * 128;
    const size_t col0 = (size_t)blockIdx.y * 128;

    float acc[4][8][4];
#pragma unroll
    for (int m = 0; m < 4; ++m)
#pragma unroll
        for (int n = 0; n < 8; ++n)
#pragma unroll
            for (int i = 0; i < 4; ++i) acc[m][n][i] = 0.f;

    auto issue = [&](int k0, int stg) {
        const uint32_t sbase = sb + stg * STG;
#pragma unroll
        for (int i = tid; i < 512; i += 128) {
            const int r = i >> 2, ch = i & 3;
            const size_t gA = (row0 + r) * D_ + k0 + ch * 8;
            const uint32_t d = sbase + r * ROWB + ch * 16;
            cp16(d + O_AH, Ahp + gA);
            cp16(d + O_AL, Alp + gA);
            cp16(d + O_B,  Bp + (col0 + r) * D_ + k0 + ch * 8);
        }
        CP_COMMIT();
    };

    issue(0, 0);
    issue(32, 1);

    const uint32_t aRow = lane & 15, aChk = lane >> 4;
    const uint32_t bRow = lane & 7,  bChk = (lane >> 3) & 1;

    for (int it = 0; it < NK_; ++it) {
        if (it + 1 < NK_) asm volatile("cp.async.wait_group 1;" ::: "memory");
        else              asm volatile("cp.async.wait_group 0;" ::: "memory");
        __syncthreads();
        if (it + 2 < NK_) issue((it + 2) * 32, (it + 2) % 3);

        const uint32_t st = sb + (it % 3) * STG;
        const uint32_t sA = st + (wm * 64) * ROWB;
        const uint32_t sB = st + O_B + (wn * 64) * ROWB;

#pragma unroll
        for (int ks = 0; ks < 2; ++ks) {
            uint32_t ah[4][4], al[4][4], bb[8][2];
#pragma unroll
            for (int m = 0; m < 4; ++m) {
                const uint32_t ad = sA + (m * 16 + aRow) * ROWB + (ks * 2 + aChk) * 16;
                LDSM4(ah[m][0], ah[m][1], ah[m][2], ah[m][3], ad + O_AH);
                LDSM4(al[m][0], al[m][1], al[m][2], al[m][3], ad + O_AL);
            }
#pragma unroll
            for (int n = 0; n < 8; ++n) {
                const uint32_t bd = sB + (n * 8 + bRow) * ROWB + (ks * 2 + bChk) * 16;
                LDSM2(bb[n][0], bb[n][1], bd);
            }
#pragma unroll
            for (int m = 0; m < 4; ++m)
#pragma unroll
                for (int n = 0; n < 8; ++n) {
                    mma16816(acc[m][n], ah[m], bb[n]);
                    mma16816(acc[m][n], al[m], bb[n]);
                }
        }
        __syncthreads();
    }

#pragma unroll
    for (int m = 0; m < 4; ++m) {
        const int r = (int)row0 + wm * 64 + m * 16 + (lane >> 2);
#pragma unroll
        for (int n = 0; n < 8; ++n) {
            const int cg = (int)col0 + wn * 64 + n * 8 + (lane & 3) * 2;
            float b0 = bias ? bias[cg] : 0.f, b1 = bias ? bias[cg + 1] : 0.f;
            float2 v0 = make_float2(acc[m][n][0] + b0, acc[m][n][1] + b1);
            float2 v1 = make_float2(acc[m][n][2] + b0, acc[m][n][3] + b1);
            *(float2*)(C + (size_t)r * N + cg) = v0;
            *(float2*)(C + (size_t)(r + 8) * N + cg) = v1;
        }
    }
}

// ---------------- rope ----------------
__global__ void rope_table()
{
    int i = blockIdx.x * 256 + threadIdx.x;
    int t = i >> 6, hf = i & 63;
    double invf = exp(-(double)hf * (9.210340371976184 / 64.0));
    double ph = (double)t * invf;
    g_trig[i] = make_float2((float)cos(ph), (float)sin(ph));
}

__global__ void rope_apply(float* __restrict__ X, int nheads, int total)
{
    int idx = blockIdx.x * 256 + threadIdx.x;
    if (idx >= total) return;
    int half = idx & 63;
    int head = (idx >> 6) % nheads;
    int row = idx / (64 * nheads);
    int t = row & (T_ - 1);
    float2 cs = g_trig[(t << 6) + half];
    size_t base = (size_t)row * nheads * HD_ + (size_t)head * HD_;
    float x1 = X[base + half], x2 = X[base + half + 64];
    X[base + half] = x1 * cs.x - x2 * cs.y;
    X[base + half + 64] = x2 * cs.x + x1 * cs.y;
}

// ---------------- HMMA flash attention (online max, softcap) -------------
// grid (T/128, NQ, B), 256 threads (8 warps x 16 q-rows)
__global__ __launch_bounds__(256) void attn_mma()
{
    extern __shared__ char smraw[];
    const uint32_t sb = smem_u32(smraw);
    const int tid = threadIdx.x, w = tid >> 5, lane = tid & 31;
    const int qt = blockIdx.x, h = blockIdx.y, b = blockIdx.z;
    const int kv = h / GRP_;
    const int g = lane >> 2, c2 = (lane & 3) * 2;
    const int rowbase = qt * 128 + w * 16;

    uint32_t qh[8][4], ql[8][4];
#pragma unroll
    for (int ks = 0; ks < 8; ++ks)
#pragma unroll
        for (int j = 0; j < 4; ++j) { qh[ks][j] = 0u; ql[ks][j] = 0u; }
#pragma unroll 1
    for (int half = 0; half < 2; ++half) {
        const float* Qg = g_Q + ((size_t)(b * T_) + qt * 128 + half * 64) * D_ + h * HD_;
        for (int i = tid; i < 2048; i += 256) {
            int r = i >> 5, ch = i & 31;
            cp16(sb + r * 512 + ch * 16, (const char*)(Qg + (size_t)r * D_) + ch * 16);
        }
        CP_COMMIT();
        asm volatile("cp.async.wait_group 0;" ::: "memory");
        __syncthreads();
        if ((w >> 2) == half) {
            int wr = (w & 3) * 16;
#pragma unroll
            for (int ks = 0; ks < 8; ++ks)
#pragma unroll
                for (int j = 0; j < 4; ++j) {
                    int row = wr + g + (j & 1) * 8;
                    int col = ks * 16 + (j >> 1) * 8 + c2;
                    float2 v = *(float2*)(smraw + row * 512 + col * 4);
                    __half hx = __float2half_rn(v.x), hy = __float2half_rn(v.y);
                    __half lx = __float2half_rn(v.x - __half2float(hx));
                    __half ly = __float2half_rn(v.y - __half2float(hy));
                    qh[ks][j] = (uint32_t)__half_as_ushort(hx) |
                                ((uint32_t)__half_as_ushort(hy) << 16);
                    ql[ks][j] = (uint32_t)__half_as_ushort(lx) |
                                ((uint32_t)__half_as_ushort(ly) << 16);
                }
        }
        __syncthreads();
    }

    float acc[17][4];
#pragma unroll
    for (int n = 0; n < 17; ++n)
#pragma unroll
        for (int i = 0; i < 4; ++i) acc[n][i] = 0.f;
    float m0 = -1e30f, m1 = -1e30f;

    const int ktmax = 4 * qt + 3;
    const int rowmax = rowbase + 15;
    const char* khg = (const char*)g_Kh + ((size_t)(b * NKV_ + kv) * T_) * HD_ * 2;
    const char* klg = (const char*)g_Kl + ((size_t)(b * NKV_ + kv) * T_) * HD_ * 2;
    const char* vtg = (const char*)g_VT + ((size_t)(b * NKV_ + kv) * 136) * T_ * 2;

    auto issueKV = [&](int kt) {
        const uint32_t sst = sb + (kt & 1) * AT_STG;
        const char* kh = khg + (size_t)kt * 32 * 256;
        const char* kl = klg + (size_t)kt * 32 * 256;
        const char* vt = vtg + (size_t)kt * 64;
        for (int i = tid; i < 1568; i += 256) {
            if (i < 512) {
                int r = i >> 4, ch = i & 15;
                cp16(sst + AT_KH + r * 272 + ch * 16, kh + r * 256 + ch * 16);
            } else if (i < 1024) {
                int j = i - 512, r = j >> 4, ch = j & 15;
                cp16(sst + AT_KL + r * 272 + ch * 16, kl + r * 256 + ch * 16);
            } else {
                int j = i - 1024, r = j >> 2, ch = j & 3;
                cp16(sst + AT_VT + r * 80 + ch * 16, vt + (size_t)r * 2048 + ch * 16);
            }
        }
        CP_COMMIT();
    };

    issueKV(0);
    for (int kt = 0; kt <= ktmax; ++kt) {
        if (kt < ktmax) {
            issueKV(kt + 1);
            asm volatile("cp.async.wait_group 1;" ::: "memory");
        } else {
            asm volatile("cp.async.wait_group 0;" ::: "memory");
        }
        __syncthreads();
        if (kt * 32 <= rowmax) {
            const uint32_t sst = sb + (kt & 1) * AT_STG;
            float lg[4][4];
#pragma unroll
            for (int nt = 0; nt < 4; ++nt) {
                float sacc[4] = {0.f, 0.f, 0.f, 0.f};
                const uint32_t ba0 = sst + (nt * 8 + (lane & 7)) * 272 +
                                     ((lane >> 3) & 1) * 16;
#pragma unroll
                for (int ks = 0; ks < 8; ++ks) {
                    uint32_t bh[2], bl[2];
                    LDSM2(bh[0], bh[1], ba0 + AT_KH + ks * 32);
                    LDSM2(bl[0], bl[1], ba0 + AT_KL + ks * 32);
                    mma16816(sacc, qh[ks], bh);
                    mma16816(sacc, ql[ks], bh);
                    mma16816(sacc, qh[ks], bl);
                }
                const int colb = kt * 32 + nt * 8 + c2;
#pragma unroll
                for (int i = 0; i < 4; ++i) {
                    int row = rowbase + g + (i >> 1) * 8;
                    int col = colb + (i & 1);
                    float u = ex2f(sacc[i] * CK_);
                    float r_ = rcpf(u + 1.0f);
                    lg[nt][i] = (col <= row) ? fmaf(-60.0f, r_, 30.0f) : -1e30f;
                }
            }
            float mx0 = fmaxf(fmaxf(fmaxf(lg[0][0], lg[0][1]), fmaxf(lg[1][0], lg[1][1])),
                              fmaxf(fmaxf(lg[2][0], lg[2][1]), fmaxf(lg[3][0], lg[3][1])));
            float mx1 = fmaxf(fmaxf(fmaxf(lg[0][2], lg[0][3]), fmaxf(lg[1][2], lg[1][3])),
                              fmaxf(fmaxf(lg[2][2], lg[2][3]), fmaxf(lg[3][2], lg[3][3])));
            mx0 = fmaxf(mx0, __shfl_xor_sync(0xffffffffu, mx0, 1));
            mx0 = fmaxf(mx0, __shfl_xor_sync(0xffffffffu, mx0, 2));
            mx1 = fmaxf(mx1, __shfl_xor_sync(0xffffffffu, mx1, 1));
            mx1 = fmaxf(mx1, __shfl_xor_sync(0xffffffffu, mx1, 2));
            float nm0 = fmaxf(m0, mx0), nm1 = fmaxf(m1, mx1);
            float s0 = ex2f((m0 - nm0) * L2E_);
            float s1 = ex2f((m1 - nm1) * L2E_);
            m0 = nm0; m1 = nm1;
#pragma unroll
            for (int n = 0; n < 17; ++n) {
                acc[n][0] *= s0; acc[n][1] *= s0;
                acc[n][2] *= s1; acc[n][3] *= s1;
            }
            uint32_t pf[4][2];
#pragma unroll
            for (int nt = 0; nt < 4; ++nt) {
                float p0 = ex2f((lg[nt][0] - m0) * L2E_);
                float p1 = ex2f((lg[nt][1] - m0) * L2E_);
                float p2 = ex2f((lg[nt][2] - m1) * L2E_);
                float p3 = ex2f((lg[nt][3] - m1) * L2E_);
                pf[nt][0] = packh2(p0, p1);
                pf[nt][1] = packh2(p2, p3);
            }
#pragma unroll
            for (int kp = 0; kp < 2; ++kp) {
                uint32_t a[4] = {pf[2 * kp][0], pf[2 * kp][1],
                                 pf[2 * kp + 1][0], pf[2 * kp + 1][1]};
                const uint32_t vb0 = sst + AT_VT + (lane & 7) * 80 +
                                     (kp * 2 + ((lane >> 3) & 1)) * 16;
#pragma unroll
                for (int n = 0; n < 17; ++n) {
                    uint32_t bv[2];
                    LDSM2(bv[0], bv[1], vb0 + n * 8 * 80);
                    mma16816(acc[n], a, bv);
                }
            }
        }
        __syncthreads();
    }

    float l0 = __shfl_sync(0xffffffffu, acc[16][0], lane & 28);
    float l1 = __shfl_sync(0xffffffffu, acc[16][2], lane & 28);
    float i0 = __fdividef(1.0f, l0);
    float i1 = __fdividef(1.0f, l1);
    const size_t r0 = (size_t)(b * T_ + rowbase + g) * D_ + h * HD_ + c2;
    const size_t r1 = r0 + (size_t)8 * D_;
#pragma unroll
    for (int nt = 0; nt < 16; ++nt) {
        float x0 = acc[nt][0] * i0, y0 = acc[nt][1] * i0;
        float x1 = acc[nt][2] * i1, y1 = acc[nt][3] * i1;
        __half hx0 = __float2half_rn(x0), hy0 = __float2half_rn(y0);
        __half hx1 = __float2half_rn(x1), hy1 = __float2half_rn(y1);
        uint32_t H0 = (uint32_t)__half_as_ushort(hx0) | ((uint32_t)__half_as_ushort(hy0) << 16);
        uint32_t L0 = (uint32_t)__half_as_ushort(__float2half_rn(x0 - __half2float(hx0))) |
                      ((uint32_t)__half_as_ushort(__float2half_rn(y0 - __half2float(hy0))) << 16);
        uint32_t H1 = (uint32_t)__half_as_ushort(hx1) | ((uint32_t)__half_as_ushort(hy1) << 16);
        uint32_t L1 = (uint32_t)__half_as_ushort(__float2half_rn(x1 - __half2float(hx1))) |
                      ((uint32_t)__half_as_ushort(__float2half_rn(y1 - __half2float(hy1))) << 16);
        *(uint32_t*)(g_Ah + r0 + nt * 8) = H0;
        *(uint32_t*)(g_Al + r0 + nt * 8) = L0;
        *(uint32_t*)(g_Ah + r1 + nt * 8) = H1;
        *(uint32_t*)(g_Al + r1 + nt * 8) = L1;
    }
}

// ---------------- launch ----------------
extern "C" void kernel_launch(void* const* d_in, const int* in_sizes, int n_in,
                              void* d_out, int out_size)
{
    (void)in_sizes; (void)n_in; (void)out_size;
    const float* query = (const float*)d_in[0];
    const float* key   = (const float*)d_in[1];
    const float* value = (const float*)d_in[2];
    const float* wq = (const float*)d_in[4];
    const float* bq = (const float*)d_in[5];
    const float* wk = (const float*)d_in[6];
    const float* bk = (const float*)d_in[7];
    const float* wv = (const float*)d_in[8];
    const float* bv = (const float*)d_in[9];
    const float* wo = (const float*)d_in[10];
    float* out = (float*)d_out;

    cudaFuncSetAttribute(gemm_mma, cudaFuncAttributeMaxDynamicSharedMemorySize, SMEM_TOT);
    cudaFuncSetAttribute(attn_mma, cudaFuncAttributeMaxDynamicSharedMemorySize, AT_SMEM);

    float *Qp, *Kp, *Vp;
    __half *Ah, *Al, *Wq, *Wk, *Wv, *Wo;
    cudaGetSymbolAddress((void**)&Qp, g_Q);
    cudaGetSymbolAddress((void**)&Kp, g_K);
    cudaGetSymbolAddress((void**)&Vp, g_V);
    cudaGetSymbolAddress((void**)&Ah, g_Ah);
    cudaGetSymbolAddress((void**)&Al, g_Al);
    cudaGetSymbolAddress((void**)&Wq, g_Wq);
    cudaGetSymbolAddress((void**)&Wk, g_Wk);
    cudaGetSymbolAddress((void**)&Wv, g_Wv);
    cudaGetSymbolAddress((void**)&Wo, g_Wo);

    const int M = B_ * T_;
    const int n4 = M * D_ / 4;

    wT_fp16<<<dim3(D_ / 32, D_ / 32), dim3(32, 8)>>>(wq, Wq, D_, D_);
    wT_fp16<<<dim3(KVD_ / 32, D_ / 32), dim3(32, 8)>>>(wk, Wk, D_, KVD_);
    wT_fp16<<<dim3(KVD_ / 32, D_ / 32), dim3(32, 8)>>>(wv, Wv, D_, KVD_);
    wT_fp16<<<dim3(D_ / 32, D_ / 32), dim3(32, 8)>>>(wo, Wo, D_, D_);
    rope_table<<<256, 256>>>();

    // projections
    split_fp16<<<(n4 + 255) / 256, 256>>>(query, Ah, Al, n4);
    gemm_mma<<<dim3(M / 128, D_ / 128), 128, SMEM_TOT>>>(Ah, Al, Wq, bq, Qp, D_);
    split_fp16<<<(n4 + 255) / 256, 256>>>(key, Ah, Al, n4);
    gemm_mma<<<dim3(M / 128, KVD_ / 128), 128, SMEM_TOT>>>(Ah, Al, Wk, bk, Kp, KVD_);
    split_fp16<<<(n4 + 255) / 256, 256>>>(value, Ah, Al, n4);
    gemm_mma<<<dim3(M / 128, KVD_ / 128), 128, SMEM_TOT>>>(Ah, Al, Wv, bv, Vp, KVD_);

    // rope
    rope_apply<<<(M * NQ_ * 64 + 255) / 256, 256>>>(Qp, NQ_, M * NQ_ * 64);
    rope_apply<<<(M * NKV_ * 64 + 255) / 256, 256>>>(Kp, NKV_, M * NKV_ * 64);

    // attention prep
    kvsplit<<<(B_ * NKV_ * T_ * 32) / 256, 256>>>(Kp);
    vtsplit<<<(16 * 136 * 256 + 255) / 256, 256>>>(Vp);

    // flash attention -> writes g_Ah/g_Al directly
    attn_mma<<<dim3(T_ / 128, NQ_, B_), 256, AT_SMEM>>>();

    // output projection
    gemm_mma<<<dim3(M / 128, D_ / 128), 128, SMEM_TOT>>>(Ah, Al, Wo, nullptr, out, D_);
}

// round 13
// speedup vs baseline: 1.1931x; 1.1931x over previous
#include <cuda_runtime.h>
#include <cuda_fp16.h>
#include <stdint.h>
#include <math.h>

#define B_   2
#define T_   1024
#define D_   6144
#define NQ_  48
#define NKV_ 8
#define HD_  128
#define GRP_ 6
#define KVD_ 1024
#define MULT_ 0.08838834764831845f
#define CK_  0.0085011611f
#define L2E_ 1.4426950408889634f

#define NK_   (D_ / 32)
#define ROWB  80
#define O_AH  0
#define O_AL  10240
#define O_B   20480
#define STG   30720
#define SMEM_TOT (3 * STG)

#define AT_KH 0
#define AT_KL 8704
#define AT_VT 17408
#define AT_STG 28288
#define AT_SMEM (2 * AT_STG)

// ---------------- scratch ----------------
__device__ __align__(128) float g_Q[(size_t)B_ * T_ * D_];
__device__ __align__(128) float g_K[(size_t)B_ * T_ * KVD_];
__device__ __align__(128) float g_V[(size_t)B_ * T_ * KVD_];
__device__ __align__(16) __half g_Ah[(size_t)B_ * T_ * D_];
__device__ __align__(16) __half g_Al[(size_t)B_ * T_ * D_];
__device__ __align__(16) __half g_KAh[(size_t)B_ * T_ * D_];
__device__ __align__(16) __half g_KAl[(size_t)B_ * T_ * D_];
__device__ __align__(16) __half g_VAh[(size_t)B_ * T_ * D_];
__device__ __align__(16) __half g_VAl[(size_t)B_ * T_ * D_];
__device__ __align__(16) __half g_Kh[(size_t)B_ * NKV_ * T_ * HD_];
__device__ __align__(16) __half g_Kl[(size_t)B_ * NKV_ * T_ * HD_];
__device__ __align__(16) __half g_VT[(size_t)B_ * NKV_ * 136 * T_];
__device__ __align__(16) __half g_Wq[(size_t)D_ * D_];
__device__ __align__(16) __half g_Wk[(size_t)KVD_ * D_];
__device__ __align__(16) __half g_Wv[(size_t)KVD_ * D_];
__device__ __align__(16) __half g_Wo[(size_t)D_ * D_];
__device__ float2 g_trig[T_ * 64];

// ---------------- ptx helpers ----------------
__device__ __forceinline__ uint32_t smem_u32(const void* p) {
    uint32_t a;
    asm("{ .reg .u64 t; cvta.to.shared.u64 t, %1; cvt.u32.u64 %0, t; }" : "=r"(a) : "l"(p));
    return a;
}
__device__ __forceinline__ void cp16(uint32_t d, const void* s) {
    asm volatile("cp.async.cg.shared.global [%0], [%1], 16;" :: "r"(d), "l"(s));
}
#define CP_COMMIT() asm volatile("cp.async.commit_group;" ::: "memory")
#define LDSM4(r0, r1, r2, r3, a) \
    asm volatile("ldmatrix.sync.aligned.m8n8.x4.shared.b16 {%0,%1,%2,%3}, [%4];" \
                 : "=r"(r0), "=r"(r1), "=r"(r2), "=r"(r3) : "r"(a))
#define LDSM2(r0, r1, a) \
    asm volatile("ldmatrix.sync.aligned.m8n8.x2.shared.b16 {%0,%1}, [%2];" \
                 : "=r"(r0), "=r"(r1) : "r"(a))
__device__ __forceinline__ void mma16816(float* c, const uint32_t* a, const uint32_t* b) {
    asm volatile(
        "mma.sync.aligned.m16n8k16.row.col.f32.f16.f16.f32 "
        "{%0,%1,%2,%3}, {%4,%5,%6,%7}, {%8,%9}, {%0,%1,%2,%3};"
        : "+f"(c[0]), "+f"(c[1]), "+f"(c[2]), "+f"(c[3])
        : "r"(a[0]), "r"(a[1]), "r"(a[2]), "r"(a[3]), "r"(b[0]), "r"(b[1]));
}
__device__ __forceinline__ uint32_t packh2(float x, float y) {
    __half2 h = __floats2half2_rn(x, y);
    return *(uint32_t*)&h;
}
__device__ __forceinline__ float ex2f(float x) {
    float r; asm("ex2.approx.f32 %0, %1;" : "=f"(r) : "f"(x)); return r;
}
__device__ __forceinline__ float rcpf(float x) {
    float r; asm("rcp.approx.f32 %0, %1;" : "=f"(r) : "f"(x)); return r;
}

// ---------------- prep kernels ----------------
__global__ __launch_bounds__(256) void wT_fp16(
    const float* __restrict__ W, __half* __restrict__ Tr, int K, int N)
{
    __shared__ float tb[32][33];
    const int n0 = blockIdx.x * 32, k0 = blockIdx.y * 32;
    const int tx = threadIdx.x, ty = threadIdx.y;
#pragma unroll
    for (int j = 0; j < 4; ++j)
        tb[ty + j * 8][tx] = W[(size_t)(k0 + ty + j * 8) * N + n0 + tx];
    __syncthreads();
#pragma unroll
    for (int j = 0; j < 4; ++j) {
        int n = ty + j * 8;
        Tr[(size_t)(n0 + n) * K + k0 + tx] = __float2half_rn(tb[tx][n]);
    }
}

__global__ __launch_bounds__(256) void split_fp16(
    const float* __restrict__ X, __half* __restrict__ H,
    __half* __restrict__ L, int n4)
{
    int i = blockIdx.x * 256 + threadIdx.x;
    if (i >= n4) return;
    float4 v = ((const float4*)X)[i];
    ushort4 hh, ll;
    float f[4] = {v.x, v.y, v.z, v.w};
    unsigned short* hp = &hh.x; unsigned short* lp = &ll.x;
#pragma unroll
    for (int k = 0; k < 4; ++k) {
        __half h = __float2half_rn(f[k]);
        __half l = __float2half_rn(f[k] - __half2float(h));
        hp[k] = __half_as_ushort(h); lp[k] = __half_as_ushort(l);
    }
    ((ushort4*)H)[i] = hh; ((ushort4*)L)[i] = ll;
}

__global__ __launch_bounds__(256) void kvsplit(const float* __restrict__ K)
{
    int i = blockIdx.x * 256 + threadIdx.x;
    int d4 = i & 31, t = (i >> 5) & (T_ - 1), kvb = i >> 15;
    int b = kvb >> 3, kv = kvb & 7;
    float4 v = *(const float4*)(K + ((size_t)(b * T_ + t) * KVD_ + kv * 128 + d4 * 4));
    ushort4 hh, ll;
    float f[4] = {v.x, v.y, v.z, v.w};
    unsigned short* hp = &hh.x; unsigned short* lp = &ll.x;
#pragma unroll
    for (int k = 0; k < 4; ++k) {
        __half h = __float2half_rn(f[k]);
        __half l = __float2half_rn(f[k] - __half2float(h));
        hp[k] = __half_as_ushort(h); lp[k] = __half_as_ushort(l);
    }
    size_t o = ((size_t)kvb * T_ + t) * 128 + d4 * 4;
    *(ushort4*)(g_Kh + o) = hh; *(ushort4*)(g_Kl + o) = ll;
}

__global__ __launch_bounds__(256) void vtsplit(const float* __restrict__ V)
{
    int i = blockIdx.x * 256 + threadIdx.x;
    if (i >= 16 * 136 * 256) return;
    int t4 = i & 255, n = (i >> 8) % 136, kvb = i / (136 * 256);
    int b = kvb >> 3, kv = kvb & 7;
    ushort4 o;
    unsigned short* op = &o.x;
    int t = t4 * 4;
#pragma unroll
    for (int j = 0; j < 4; ++j) {
        float x = (n < 128) ? V[(size_t)(b * T_ + t + j) * KVD_ + kv * 128 + n]
                            : (n == 128 ? 1.0f : 0.0f);
        op[j] = __half_as_ushort(__float2half_rn(x));
    }
    *(ushort4*)(g_VT + ((size_t)kvb * 136 + n) * T_ + t) = o;
}

// ---------------- shared GEMM body: 128x128 CTA, 4 warps, 64x64 tiles ----
__device__ __forceinline__ void gemm_body(
    const __half* __restrict__ Ahp, const __half* __restrict__ Alp,
    const __half* __restrict__ Bp,
    const float* __restrict__ bias, float* __restrict__ C, int N,
    int bx, int by, char* smraw)
{
    const uint32_t sb = smem_u32(smraw);
    const int tid = threadIdx.x, wid = tid >> 5, lane = tid & 31;
    const int wm = wid & 1, wn = wid >> 1;
    const size_t row0 = (size_t)bx * 128;
    const size_t col0 = (size_t)by * 128;

    float acc[4][8][4];
#pragma unroll
    for (int m = 0; m < 4; ++m)
#pragma unroll
        for (int n = 0; n < 8; ++n)
#pragma unroll
            for (int i = 0; i < 4; ++i) acc[m][n][i] = 0.f;

    auto issue = [&](int k0, int stg) {
        const uint32_t sbase = sb + stg * STG;
#pragma unroll
        for (int i = tid; i < 512; i += 128) {
            const int r = i >> 2, ch = i & 3;
            const size_t gA = (row0 + r) * D_ + k0 + ch * 8;
            const uint32_t d = sbase + r * ROWB + ch * 16;
            cp16(d + O_AH, Ahp + gA);
            cp16(d + O_AL, Alp + gA);
            cp16(d + O_B,  Bp + (col0 + r) * D_ + k0 + ch * 8);
        }
        CP_COMMIT();
    };

    issue(0, 0);
    issue(32, 1);

    const uint32_t aRow = lane & 15, aChk = lane >> 4;
    const uint32_t bRow = lane & 7,  bChk = (lane >> 3) & 1;

    for (int it = 0; it < NK_; ++it) {
        if (it + 1 < NK_) asm volatile("cp.async.wait_group 1;" ::: "memory");
        else              asm volatile("cp.async.wait_group 0;" ::: "memory");
        __syncthreads();
        if (it + 2 < NK_) issue((it + 2) * 32, (it + 2) % 3);

        const uint32_t st = sb + (it % 3) * STG;
        const uint32_t sA = st + (wm * 64) * ROWB;
        const uint32_t sB = st + O_B + (wn * 64) * ROWB;

#pragma unroll
        for (int ks = 0; ks < 2; ++ks) {
            uint32_t ah[4][4], al[4][4], bb[8][2];
#pragma unroll
            for (int m = 0; m < 4; ++m) {
                const uint32_t ad = sA + (m * 16 + aRow) * ROWB + (ks * 2 + aChk) * 16;
                LDSM4(ah[m][0], ah[m][1], ah[m][2], ah[m][3], ad + O_AH);
                LDSM4(al[m][0], al[m][1], al[m][2], al[m][3], ad + O_AL);
            }
#pragma unroll
            for (int n = 0; n < 8; ++n) {
                const uint32_t bd = sB + (n * 8 + bRow) * ROWB + (ks * 2 + bChk) * 16;
                LDSM2(bb[n][0], bb[n][1], bd);
            }
#pragma unroll
            for (int m = 0; m < 4; ++m)
#pragma unroll
                for (int n = 0; n < 8; ++n) {
                    mma16816(acc[m][n], ah[m], bb[n]);
                    mma16816(acc[m][n], al[m], bb[n]);
                }
        }
        // no trailing sync: stage (it+2)%3 was last read at iter it-1,
        // which precedes this iteration's top __syncthreads for all threads.
    }

#pragma unroll
    for (int m = 0; m < 4; ++m) {
        const int r = (int)row0 + wm * 64 + m * 16 + (lane >> 2);
#pragma unroll
        for (int n = 0; n < 8; ++n) {
            const int cg = (int)col0 + wn * 64 + n * 8 + (lane & 3) * 2;
            float b0 = bias ? bias[cg] : 0.f, b1 = bias ? bias[cg + 1] : 0.f;
            float2 v0 = make_float2(acc[m][n][0] + b0, acc[m][n][1] + b1);
            float2 v1 = make_float2(acc[m][n][2] + b0, acc[m][n][3] + b1);
            *(float2*)(C + (size_t)r * N + cg) = v0;
            *(float2*)(C + (size_t)(r + 8) * N + cg) = v1;
        }
    }
}

// O-projection (and generic) wrapper
__global__ __launch_bounds__(128, 2) void gemm_mma(
    const __half* __restrict__ Ahp, const __half* __restrict__ Alp,
    const __half* __restrict__ Bp,
    const float* __restrict__ bias, float* __restrict__ C, int N)
{
    extern __shared__ char smraw[];
    gemm_body(Ahp, Alp, Bp, bias, C, N, blockIdx.x, blockIdx.y, smraw);
}

// Fused Q+K+V projections: 1024 CTAs, linear id decode
__global__ __launch_bounds__(128, 2) void gemm_qkv(
    const float* __restrict__ bq, const float* __restrict__ bk,
    const float* __restrict__ bv)
{
    extern __shared__ char smraw[];
    const int id = blockIdx.x;
    const __half *Ah, *Al, *Bw;
    const float* bias;
    float* C;
    int N, bx, by;
    if (id < 768) {                 // Q: 16 x 48
        Ah = g_Ah;  Al = g_Al;  Bw = g_Wq; bias = bq; C = g_Q; N = D_;
        bx = id & 15; by = id >> 4;
    } else if (id < 896) {          // K: 16 x 8
        int j = id - 768;
        Ah = g_KAh; Al = g_KAl; Bw = g_Wk; bias = bk; C = g_K; N = KVD_;
        bx = j & 15; by = j >> 4;
    } else {                        // V: 16 x 8
        int j = id - 896;
        Ah = g_VAh; Al = g_VAl; Bw = g_Wv; bias = bv; C = g_V; N = KVD_;
        bx = j & 15; by = j >> 4;
    }
    gemm_body(Ah, Al, Bw, bias, C, N, bx, by, smraw);
}

// ---------------- rope ----------------
__global__ void rope_table()
{
    int i = blockIdx.x * 256 + threadIdx.x;
    int t = i >> 6, hf = i & 63;
    double invf = exp(-(double)hf * (9.210340371976184 / 64.0));
    double ph = (double)t * invf;
    g_trig[i] = make_float2((float)cos(ph), (float)sin(ph));
}

__global__ void rope_apply(float* __restrict__ X, int nheads, int total)
{
    int idx = blockIdx.x * 256 + threadIdx.x;
    if (idx >= total) return;
    int half = idx & 63;
    int head = (idx >> 6) % nheads;
    int row = idx / (64 * nheads);
    int t = row & (T_ - 1);
    float2 cs = g_trig[(t << 6) + half];
    size_t base = (size_t)row * nheads * HD_ + (size_t)head * HD_;
    float x1 = X[base + half], x2 = X[base + half + 64];
    X[base + half] = x1 * cs.x - x2 * cs.y;
    X[base + half + 64] = x2 * cs.x + x1 * cs.y;
}

// ---------------- HMMA flash attention (online max, softcap) -------------
__global__ __launch_bounds__(256) void attn_mma()
{
    extern __shared__ char smraw[];
    const uint32_t sb = smem_u32(smraw);
    const int tid = threadIdx.x, w = tid >> 5, lane = tid & 31;
    const int qt = blockIdx.x, h = blockIdx.y, b = blockIdx.z;
    const int kv = h / GRP_;
    const int g = lane >> 2, c2 = (lane & 3) * 2;
    const int rowbase = qt * 128 + w * 16;

    uint32_t qh[8][4], ql[8][4];
#pragma unroll
    for (int ks = 0; ks < 8; ++ks)
#pragma unroll
        for (int j = 0; j < 4; ++j) { qh[ks][j] = 0u; ql[ks][j] = 0u; }
#pragma unroll 1
    for (int half = 0; half < 2; ++half) {
        const float* Qg = g_Q + ((size_t)(b * T_) + qt * 128 + half * 64) * D_ + h * HD_;
        for (int i = tid; i < 2048; i += 256) {
            int r = i >> 5, ch = i & 31;
            cp16(sb + r * 512 + ch * 16, (const char*)(Qg + (size_t)r * D_) + ch * 16);
        }
        CP_COMMIT();
        asm volatile("cp.async.wait_group 0;" ::: "memory");
        __syncthreads();
        if ((w >> 2) == half) {
            int wr = (w & 3) * 16;
#pragma unroll
            for (int ks = 0; ks < 8; ++ks)
#pragma unroll
                for (int j = 0; j < 4; ++j) {
                    int row = wr + g + (j & 1) * 8;
                    int col = ks * 16 + (j >> 1) * 8 + c2;
                    float2 v = *(float2*)(smraw + row * 512 + col * 4);
                    __half hx = __float2half_rn(v.x), hy = __float2half_rn(v.y);
                    __half lx = __float2half_rn(v.x - __half2float(hx));
                    __half ly = __float2half_rn(v.y - __half2float(hy));
                    qh[ks][j] = (uint32_t)__half_as_ushort(hx) |
                                ((uint32_t)__half_as_ushort(hy) << 16);
                    ql[ks][j] = (uint32_t)__half_as_ushort(lx) |
                                ((uint32_t)__half_as_ushort(ly) << 16);
                }
        }
        __syncthreads();
    }

    float acc[17][4];
#pragma unroll
    for (int n = 0; n < 17; ++n)
#pragma unroll
        for (int i = 0; i < 4; ++i) acc[n][i] = 0.f;
    float m0 = -1e30f, m1 = -1e30f;

    const int ktmax = 4 * qt + 3;
    const int rowmax = rowbase + 15;
    const char* khg = (const char*)g_Kh + ((size_t)(b * NKV_ + kv) * T_) * HD_ * 2;
    const char* klg = (const char*)g_Kl + ((size_t)(b * NKV_ + kv) * T_) * HD_ * 2;
    const char* vtg = (const char*)g_VT + ((size_t)(b * NKV_ + kv) * 136) * T_ * 2;

    auto issueKV = [&](int kt) {
        const uint32_t sst = sb + (kt & 1) * AT_STG;
        const char* kh = khg + (size_t)kt * 32 * 256;
        const char* kl = klg + (size_t)kt * 32 * 256;
        const char* vt = vtg + (size_t)kt * 64;
        for (int i = tid; i < 1568; i += 256) {
            if (i < 512) {
                int r = i >> 4, ch = i & 15;
                cp16(sst + AT_KH + r * 272 + ch * 16, kh + r * 256 + ch * 16);
            } else if (i < 1024) {
                int j = i - 512, r = j >> 4, ch = j & 15;
                cp16(sst + AT_KL + r * 272 + ch * 16, kl + r * 256 + ch * 16);
            } else {
                int j = i - 1024, r = j >> 2, ch = j & 3;
                cp16(sst + AT_VT + r * 80 + ch * 16, vt + (size_t)r * 2048 + ch * 16);
            }
        }
        CP_COMMIT();
    };

    issueKV(0);
    for (int kt = 0; kt <= ktmax; ++kt) {
        if (kt < ktmax) {
            issueKV(kt + 1);
            asm volatile("cp.async.wait_group 1;" ::: "memory");
        } else {
            asm volatile("cp.async.wait_group 0;" ::: "memory");
        }
        __syncthreads();
        if (kt * 32 <= rowmax) {
            const uint32_t sst = sb + (kt & 1) * AT_STG;
            float lg[4][4];
#pragma unroll
            for (int nt = 0; nt < 4; ++nt) {
                float sacc[4] = {0.f, 0.f, 0.f, 0.f};
                const uint32_t ba0 = sst + (nt * 8 + (lane & 7)) * 272 +
                                     ((lane >> 3) & 1) * 16;
#pragma unroll
                for (int ks = 0; ks < 8; ++ks) {
                    uint32_t bh[2], bl[2];
                    LDSM2(bh[0], bh[1], ba0 + AT_KH + ks * 32);
                    LDSM2(bl[0], bl[1], ba0 + AT_KL + ks * 32);
                    mma16816(sacc, qh[ks], bh);
                    mma16816(sacc, ql[ks], bh);
                    mma16816(sacc, qh[ks], bl);
                }
                const int colb = kt * 32 + nt * 8 + c2;
#pragma unroll
                for (int i = 0; i < 4; ++i) {
                    int row = rowbase + g + (i >> 1) * 8;
                    int col = colb + (i & 1);
                    float u = ex2f(sacc[i] * CK_);
                    float r_ = rcpf(u + 1.0f);
                    lg[nt][i] = (col <= row) ? fmaf(-60.0f, r_, 30.0f) : -1e30f;
                }
            }
            float mx0 = fmaxf(fmaxf(fmaxf(lg[0][0], lg[0][1]), fmaxf(lg[1][0], lg[1][1])),
                              fmaxf(fmaxf(lg[2][0], lg[2][1]), fmaxf(lg[3][0], lg[3][1])));
            float mx1 = fmaxf(fmaxf(fmaxf(lg[0][2], lg[0][3]), fmaxf(lg[1][2], lg[1][3])),
                              fmaxf(fmaxf(lg[2][2], lg[2][3]), fmaxf(lg[3][2], lg[3][3])));
            mx0 = fmaxf(mx0, __shfl_xor_sync(0xffffffffu, mx0, 1));
            mx0 = fmaxf(mx0, __shfl_xor_sync(0xffffffffu, mx0, 2));
            mx1 = fmaxf(mx1, __shfl_xor_sync(0xffffffffu, mx1, 1));
            mx1 = fmaxf(mx1, __shfl_xor_sync(0xffffffffu, mx1, 2));
            float nm0 = fmaxf(m0, mx0), nm1 = fmaxf(m1, mx1);
            float s0 = ex2f((m0 - nm0) * L2E_);
            float s1 = ex2f((m1 - nm1) * L2E_);
            m0 = nm0; m1 = nm1;
#pragma unroll
            for (int n = 0; n < 17; ++n) {
                acc[n][0] *= s0; acc[n][1] *= s0;
                acc[n][2] *= s1; acc[n][3] *= s1;
            }
            uint32_t pf[4][2];
#pragma unroll
            for (int nt = 0; nt < 4; ++nt) {
                float p0 = ex2f((lg[nt][0] - m0) * L2E_);
                float p1 = ex2f((lg[nt][1] - m0) * L2E_);
                float p2 = ex2f((lg[nt][2] - m1) * L2E_);
                float p3 = ex2f((lg[nt][3] - m1) * L2E_);
                pf[nt][0] = packh2(p0, p1);
                pf[nt][1] = packh2(p2, p3);
            }
#pragma unroll
            for (int kp = 0; kp < 2; ++kp) {
                uint32_t a[4] = {pf[2 * kp][0], pf[2 * kp][1],
                                 pf[2 * kp + 1][0], pf[2 * kp + 1][1]};
                const uint32_t vb0 = sst + AT_VT + (lane & 7) * 80 +
                                     (kp * 2 + ((lane >> 3) & 1)) * 16;
#pragma unroll
                for (int n = 0; n < 17; ++n) {
                    uint32_t bv[2];
                    LDSM2(bv[0], bv[1], vb0 + n * 8 * 80);
                    mma16816(acc[n], a, bv);
                }
            }
        }
        __syncthreads();
    }

    float l0 = __shfl_sync(0xffffffffu, acc[16][0], lane & 28);
    float l1 = __shfl_sync(0xffffffffu, acc[16][2], lane & 28);
    float i0 = __fdividef(1.0f, l0);
    float i1 = __fdividef(1.0f, l1);
    const size_t r0 = (size_t)(b * T_ + rowbase + g) * D_ + h * HD_ + c2;
    const size_t r1 = r0 + (size_t)8 * D_;
#pragma unroll
    for (int nt = 0; nt < 16; ++nt) {
        float x0 = acc[nt][0] * i0, y0 = acc[nt][1] * i0;
        float x1 = acc[nt][2] * i1, y1 = acc[nt][3] * i1;
        __half hx0 = __float2half_rn(x0), hy0 = __float2half_rn(y0);
        __half hx1 = __float2half_rn(x1), hy1 = __float2half_rn(y1);
        uint32_t H0 = (uint32_t)__half_as_ushort(hx0) | ((uint32_t)__half_as_ushort(hy0) << 16);
        uint32_t L0 = (uint32_t)__half_as_ushort(__float2half_rn(x0 - __half2float(hx0))) |
                      ((uint32_t)__half_as_ushort(__float2half_rn(y0 - __half2float(hy0))) << 16);
        uint32_t H1 = (uint32_t)__half_as_ushort(hx1) | ((uint32_t)__half_as_ushort(hy1) << 16);
        uint32_t L1 = (uint32_t)__half_as_ushort(__float2half_rn(x1 - __half2float(hx1))) |
                      ((uint32_t)__half_as_ushort(__float2half_rn(y1 - __half2float(hy1))) << 16);
        *(uint32_t*)(g_Ah + r0 + nt * 8) = H0;
        *(uint32_t*)(g_Al + r0 + nt * 8) = L0;
        *(uint32_t*)(g_Ah + r1 + nt * 8) = H1;
        *(uint32_t*)(g_Al + r1 + nt * 8) = L1;
    }
}

// ---------------- launch ----------------
extern "C" void kernel_launch(void* const* d_in, const int* in_sizes, int n_in,
                              void* d_out, int out_size)
{
    (void)in_sizes; (void)n_in; (void)out_size;
    const float* query = (const float*)d_in[0];
    const float* key   = (const float*)d_in[1];
    const float* value = (const float*)d_in[2];
    const float* wq = (const float*)d_in[4];
    const float* bq = (const float*)d_in[5];
    const float* wk = (const float*)d_in[6];
    const float* bk = (const float*)d_in[7];
    const float* wv = (const float*)d_in[8];
    const float* bv = (const float*)d_in[9];
    const float* wo = (const float*)d_in[10];
    float* out = (float*)d_out;

    cudaFuncSetAttribute(gemm_mma, cudaFuncAttributeMaxDynamicSharedMemorySize, SMEM_TOT);
    cudaFuncSetAttribute(gemm_qkv, cudaFuncAttributeMaxDynamicSharedMemorySize, SMEM_TOT);
    cudaFuncSetAttribute(attn_mma, cudaFuncAttributeMaxDynamicSharedMemorySize, AT_SMEM);

    float *Qp, *Kp, *Vp;
    __half *Ah, *Al, *KAh, *KAl, *VAh, *VAl, *Wq, *Wk, *Wv, *Wo;
    cudaGetSymbolAddress((void**)&Qp, g_Q);
    cudaGetSymbolAddress((void**)&Kp, g_K);
    cudaGetSymbolAddress((void**)&Vp, g_V);
    cudaGetSymbolAddress((void**)&Ah, g_Ah);
    cudaGetSymbolAddress((void**)&Al, g_Al);
    cudaGetSymbolAddress((void**)&KAh, g_KAh);
    cudaGetSymbolAddress((void**)&KAl, g_KAl);
    cudaGetSymbolAddress((void**)&VAh, g_VAh);
    cudaGetSymbolAddress((void**)&VAl, g_VAl);
    cudaGetSymbolAddress((void**)&Wq, g_Wq);
    cudaGetSymbolAddress((void**)&Wk, g_Wk);
    cudaGetSymbolAddress((void**)&Wv, g_Wv);
    cudaGetSymbolAddress((void**)&Wo, g_Wo);

    const int M = B_ * T_;
    const int n4 = M * D_ / 4;

    wT_fp16<<<dim3(D_ / 32, D_ / 32), dim3(32, 8)>>>(wq, Wq, D_, D_);
    wT_fp16<<<dim3(KVD_ / 32, D_ / 32), dim3(32, 8)>>>(wk, Wk, D_, KVD_);
    wT_fp16<<<dim3(KVD_ / 32, D_ / 32), dim3(32, 8)>>>(wv, Wv, D_, KVD_);
    wT_fp16<<<dim3(D_ / 32, D_ / 32), dim3(32, 8)>>>(wo, Wo, D_, D_);
    rope_table<<<256, 256>>>();

    // splits (Q -> g_Ah/g_Al, K -> g_KAh/g_KAl, V -> g_VAh/g_VAl)
    split_fp16<<<(n4 + 255) / 256, 256>>>(query, Ah, Al, n4);
    split_fp16<<<(n4 + 255) / 256, 256>>>(key, KAh, KAl, n4);
    split_fp16<<<(n4 + 255) / 256, 256>>>(value, VAh, VAl, n4);

    // fused Q+K+V projection: 1024 CTAs
    gemm_qkv<<<1024, 128, SMEM_TOT>>>(bq, bk, bv);

    // rope
    rope_apply<<<(M * NQ_ * 64 + 255) / 256, 256>>>(Qp, NQ_, M * NQ_ * 64);
    rope_apply<<<(M * NKV_ * 64 + 255) / 256, 256>>>(Kp, NKV_, M * NKV_ * 64);

    // attention prep
    kvsplit<<<(B_ * NKV_ * T_ * 32) / 256, 256>>>(Kp);
    vtsplit<<<(16 * 136 * 256 + 255) / 256, 256>>>(Vp);

    // flash attention -> writes g_Ah/g_Al directly
    attn_mma<<<dim3(T_ / 128, NQ_, B_), 256, AT_SMEM>>>();

    // output projection
    gemm_mma<<<dim3(M / 128, D_ / 128), 128, SMEM_TOT>>>(Ah, Al, Wo, nullptr, out, D_);
}

// round 14
// speedup vs baseline: 1.3672x; 1.1459x over previous
#include <cuda_runtime.h>
#include <cuda_fp16.h>
#include <stdint.h>
#include <math.h>

#define B_   2
#define T_   1024
#define D_   6144
#define NQ_  48
#define NKV_ 8
#define HD_  128
#define GRP_ 6
#define KVD_ 1024
#define MULT_ 0.08838834764831845f
#define CK_  0.0085011611f
#define L2E_ 1.4426950408889634f

#define NK_   (D_ / 32)
#define ROWB  80
/* 2-stream (QKV) gemm smem */
#define O_AH  0
#define O_AL  10240
#define O_B   20480
#define STG   30720
#define SMEM_TOT (3 * STG)
/* 1-stream (O-proj) gemm smem */
#define P_A   0
#define P_B   10240
#define STG1  20480
#define SMEM_O (3 * STG1)

#define AT_KH 0
#define AT_KL 8704
#define AT_VT 17408
#define AT_STG 28288
#define AT_SMEM (2 * AT_STG)

// ---------------- scratch ----------------
__device__ __align__(128) float g_Q[(size_t)B_ * T_ * D_];
__device__ __align__(128) float g_K[(size_t)B_ * T_ * KVD_];
__device__ __align__(128) float g_V[(size_t)B_ * T_ * KVD_];
__device__ __align__(16) __half g_Ah[(size_t)B_ * T_ * D_];
__device__ __align__(16) __half g_Al[(size_t)B_ * T_ * D_];
__device__ __align__(16) __half g_KAh[(size_t)B_ * T_ * D_];
__device__ __align__(16) __half g_KAl[(size_t)B_ * T_ * D_];
__device__ __align__(16) __half g_VAh[(size_t)B_ * T_ * D_];
__device__ __align__(16) __half g_VAl[(size_t)B_ * T_ * D_];
__device__ __align__(16) __half g_Kh[(size_t)B_ * NKV_ * T_ * HD_];
__device__ __align__(16) __half g_Kl[(size_t)B_ * NKV_ * T_ * HD_];
__device__ __align__(16) __half g_VT[(size_t)B_ * NKV_ * 136 * T_];
__device__ __align__(16) __half g_Wq[(size_t)D_ * D_];
__device__ __align__(16) __half g_Wk[(size_t)KVD_ * D_];
__device__ __align__(16) __half g_Wv[(size_t)KVD_ * D_];
__device__ __align__(16) __half g_Wo[(size_t)D_ * D_];
__device__ float2 g_trig[T_ * 64];

// ---------------- ptx helpers ----------------
__device__ __forceinline__ uint32_t smem_u32(const void* p) {
    uint32_t a;
    asm("{ .reg .u64 t; cvta.to.shared.u64 t, %1; cvt.u32.u64 %0, t; }" : "=r"(a) : "l"(p));
    return a;
}
__device__ __forceinline__ void cp16(uint32_t d, const void* s) {
    asm volatile("cp.async.cg.shared.global [%0], [%1], 16;" :: "r"(d), "l"(s));
}
#define CP_COMMIT() asm volatile("cp.async.commit_group;" ::: "memory")
#define LDSM4(r0, r1, r2, r3, a) \
    asm volatile("ldmatrix.sync.aligned.m8n8.x4.shared.b16 {%0,%1,%2,%3}, [%4];" \
                 : "=r"(r0), "=r"(r1), "=r"(r2), "=r"(r3) : "r"(a))
#define LDSM2(r0, r1, a) \
    asm volatile("ldmatrix.sync.aligned.m8n8.x2.shared.b16 {%0,%1}, [%2];" \
                 : "=r"(r0), "=r"(r1) : "r"(a))
__device__ __forceinline__ void mma16816(float* c, const uint32_t* a, const uint32_t* b) {
    asm volatile(
        "mma.sync.aligned.m16n8k16.row.col.f32.f16.f16.f32 "
        "{%0,%1,%2,%3}, {%4,%5,%6,%7}, {%8,%9}, {%0,%1,%2,%3};"
        : "+f"(c[0]), "+f"(c[1]), "+f"(c[2]), "+f"(c[3])
        : "r"(a[0]), "r"(a[1]), "r"(a[2]), "r"(a[3]), "r"(b[0]), "r"(b[1]));
}
__device__ __forceinline__ uint32_t packh2(float x, float y) {
    __half2 h = __floats2half2_rn(x, y);
    return *(uint32_t*)&h;
}
__device__ __forceinline__ float ex2f(float x) {
    float r; asm("ex2.approx.f32 %0, %1;" : "=f"(r) : "f"(x)); return r;
}
__device__ __forceinline__ float rcpf(float x) {
    float r; asm("rcp.approx.f32 %0, %1;" : "=f"(r) : "f"(x)); return r;
}

// ---------------- prep kernels ----------------
__global__ __launch_bounds__(256) void wT_fp16(
    const float* __restrict__ W, __half* __restrict__ Tr, int K, int N)
{
    __shared__ float tb[32][33];
    const int n0 = blockIdx.x * 32, k0 = blockIdx.y * 32;
    const int tx = threadIdx.x, ty = threadIdx.y;
#pragma unroll
    for (int j = 0; j < 4; ++j)
        tb[ty + j * 8][tx] = W[(size_t)(k0 + ty + j * 8) * N + n0 + tx];
    __syncthreads();
#pragma unroll
    for (int j = 0; j < 4; ++j) {
        int n = ty + j * 8;
        Tr[(size_t)(n0 + n) * K + k0 + tx] = __float2half_rn(tb[tx][n]);
    }
}

// fused 3-way fp32 -> fp16 hi/lo split (query/key/value)
__global__ __launch_bounds__(256) void split3(
    const float* __restrict__ q, const float* __restrict__ k,
    const float* __restrict__ v, int n4)
{
    int i = blockIdx.x * 256 + threadIdx.x;
    if (i >= 3 * n4) return;
    const float* X;
    __half *H, *L;
    if (i < n4)          { X = q; H = g_Ah;  L = g_Al;  }
    else if (i < 2 * n4) { X = k; H = g_KAh; L = g_KAl; i -= n4; }
    else                 { X = v; H = g_VAh; L = g_VAl; i -= 2 * n4; }
    float4 val = ((const float4*)X)[i];
    ushort4 hh, ll;
    float f[4] = {val.x, val.y, val.z, val.w};
    unsigned short* hp = &hh.x; unsigned short* lp = &ll.x;
#pragma unroll
    for (int j = 0; j < 4; ++j) {
        __half h = __float2half_rn(f[j]);
        __half l = __float2half_rn(f[j] - __half2float(h));
        hp[j] = __half_as_ushort(h); lp[j] = __half_as_ushort(l);
    }
    ((ushort4*)H)[i] = hh; ((ushort4*)L)[i] = ll;
}

__global__ __launch_bounds__(256) void kvsplit(const float* __restrict__ K)
{
    int i = blockIdx.x * 256 + threadIdx.x;
    int d4 = i & 31, t = (i >> 5) & (T_ - 1), kvb = i >> 15;
    int b = kvb >> 3, kv = kvb & 7;
    float4 v = *(const float4*)(K + ((size_t)(b * T_ + t) * KVD_ + kv * 128 + d4 * 4));
    ushort4 hh, ll;
    float f[4] = {v.x, v.y, v.z, v.w};
    unsigned short* hp = &hh.x; unsigned short* lp = &ll.x;
#pragma unroll
    for (int k = 0; k < 4; ++k) {
        __half h = __float2half_rn(f[k]);
        __half l = __float2half_rn(f[k] - __half2float(h));
        hp[k] = __half_as_ushort(h); lp[k] = __half_as_ushort(l);
    }
    size_t o = ((size_t)kvb * T_ + t) * 128 + d4 * 4;
    *(ushort4*)(g_Kh + o) = hh; *(ushort4*)(g_Kl + o) = ll;
}

__global__ __launch_bounds__(256) void vtsplit(const float* __restrict__ V)
{
    int i = blockIdx.x * 256 + threadIdx.x;
    if (i >= 16 * 136 * 256) return;
    int t4 = i & 255, n = (i >> 8) % 136, kvb = i / (136 * 256);
    int b = kvb >> 3, kv = kvb & 7;
    ushort4 o;
    unsigned short* op = &o.x;
    int t = t4 * 4;
#pragma unroll
    for (int j = 0; j < 4; ++j) {
        float x = (n < 128) ? V[(size_t)(b * T_ + t + j) * KVD_ + kv * 128 + n]
                            : (n == 128 ? 1.0f : 0.0f);
        op[j] = __half_as_ushort(__float2half_rn(x));
    }
    *(ushort4*)(g_VT + ((size_t)kvb * 136 + n) * T_ + t) = o;
}

// ---------------- 2-stream GEMM body (QKV projections) ----------------
__device__ __forceinline__ void gemm_body(
    const __half* __restrict__ Ahp, const __half* __restrict__ Alp,
    const __half* __restrict__ Bp,
    const float* __restrict__ bias, float* __restrict__ C, int N,
    int bx, int by, char* smraw)
{
    const uint32_t sb = smem_u32(smraw);
    const int tid = threadIdx.x, wid = tid >> 5, lane = tid & 31;
    const int wm = wid & 1, wn = wid >> 1;
    const size_t row0 = (size_t)bx * 128;
    const size_t col0 = (size_t)by * 128;

    float acc[4][8][4];
#pragma unroll
    for (int m = 0; m < 4; ++m)
#pragma unroll
        for (int n = 0; n < 8; ++n)
#pragma unroll
            for (int i = 0; i < 4; ++i) acc[m][n][i] = 0.f;

    auto issue = [&](int k0, int stg) {
        const uint32_t sbase = sb + stg * STG;
#pragma unroll
        for (int i = tid; i < 512; i += 128) {
            const int r = i >> 2, ch = i & 3;
            const size_t gA = (row0 + r) * D_ + k0 + ch * 8;
            const uint32_t d = sbase + r * ROWB + ch * 16;
            cp16(d + O_AH, Ahp + gA);
            cp16(d + O_AL, Alp + gA);
            cp16(d + O_B,  Bp + (col0 + r) * D_ + k0 + ch * 8);
        }
        CP_COMMIT();
    };

    issue(0, 0);
    issue(32, 1);

    const uint32_t aRow = lane & 15, aChk = lane >> 4;
    const uint32_t bRow = lane & 7,  bChk = (lane >> 3) & 1;

    for (int it = 0; it < NK_; ++it) {
        if (it + 1 < NK_) asm volatile("cp.async.wait_group 1;" ::: "memory");
        else              asm volatile("cp.async.wait_group 0;" ::: "memory");
        __syncthreads();
        if (it + 2 < NK_) issue((it + 2) * 32, (it + 2) % 3);

        const uint32_t st = sb + (it % 3) * STG;
        const uint32_t sA = st + (wm * 64) * ROWB;
        const uint32_t sB = st + O_B + (wn * 64) * ROWB;

#pragma unroll
        for (int ks = 0; ks < 2; ++ks) {
            uint32_t ah[4][4], al[4][4], bb[8][2];
#pragma unroll
            for (int m = 0; m < 4; ++m) {
                const uint32_t ad = sA + (m * 16 + aRow) * ROWB + (ks * 2 + aChk) * 16;
                LDSM4(ah[m][0], ah[m][1], ah[m][2], ah[m][3], ad + O_AH);
                LDSM4(al[m][0], al[m][1], al[m][2], al[m][3], ad + O_AL);
            }
#pragma unroll
            for (int n = 0; n < 8; ++n) {
                const uint32_t bd = sB + (n * 8 + bRow) * ROWB + (ks * 2 + bChk) * 16;
                LDSM2(bb[n][0], bb[n][1], bd);
            }
#pragma unroll
            for (int m = 0; m < 4; ++m)
#pragma unroll
                for (int n = 0; n < 8; ++n) {
                    mma16816(acc[m][n], ah[m], bb[n]);
                    mma16816(acc[m][n], al[m], bb[n]);
                }
        }
    }

#pragma unroll
    for (int m = 0; m < 4; ++m) {
        const int r = (int)row0 + wm * 64 + m * 16 + (lane >> 2);
#pragma unroll
        for (int n = 0; n < 8; ++n) {
            const int cg = (int)col0 + wn * 64 + n * 8 + (lane & 3) * 2;
            float b0 = bias ? bias[cg] : 0.f, b1 = bias ? bias[cg + 1] : 0.f;
            float2 v0 = make_float2(acc[m][n][0] + b0, acc[m][n][1] + b1);
            float2 v1 = make_float2(acc[m][n][2] + b0, acc[m][n][3] + b1);
            *(float2*)(C + (size_t)r * N + cg) = v0;
            *(float2*)(C + (size_t)(r + 8) * N + cg) = v1;
        }
    }
}

// Fused Q+K+V projections: 1024 CTAs
__global__ __launch_bounds__(128, 2) void gemm_qkv(
    const float* __restrict__ bq, const float* __restrict__ bk,
    const float* __restrict__ bv)
{
    extern __shared__ char smraw[];
    const int id = blockIdx.x;
    const __half *Ah, *Al, *Bw;
    const float* bias;
    float* C;
    int N, bx, by;
    if (id < 768) {
        Ah = g_Ah;  Al = g_Al;  Bw = g_Wq; bias = bq; C = g_Q; N = D_;
        bx = id & 15; by = id >> 4;
    } else if (id < 896) {
        int j = id - 768;
        Ah = g_KAh; Al = g_KAl; Bw = g_Wk; bias = bk; C = g_K; N = KVD_;
        bx = j & 15; by = j >> 4;
    } else {
        int j = id - 896;
        Ah = g_VAh; Al = g_VAl; Bw = g_Wv; bias = bv; C = g_V; N = KVD_;
        bx = j & 15; by = j >> 4;
    }
    gemm_body(Ah, Al, Bw, bias, C, N, bx, by, smraw);
}

// ---------------- 1-stream GEMM (O projection) ----------------
__global__ __launch_bounds__(128, 2) void gemm_o(
    const __half* __restrict__ Ahp, const __half* __restrict__ Bp,
    float* __restrict__ C, int N)
{
    extern __shared__ char smraw[];
    const uint32_t sb = smem_u32(smraw);
    const int tid = threadIdx.x, wid = tid >> 5, lane = tid & 31;
    const int wm = wid & 1, wn = wid >> 1;
    const size_t row0 = (size_t)blockIdx.x * 128;
    const size_t col0 = (size_t)blockIdx.y * 128;

    float acc[4][8][4];
#pragma unroll
    for (int m = 0; m < 4; ++m)
#pragma unroll
        for (int n = 0; n < 8; ++n)
#pragma unroll
            for (int i = 0; i < 4; ++i) acc[m][n][i] = 0.f;

    auto issue = [&](int k0, int stg) {
        const uint32_t sbase = sb + stg * STG1;
#pragma unroll
        for (int i = tid; i < 512; i += 128) {
            const int r = i >> 2, ch = i & 3;
            const uint32_t d = sbase + r * ROWB + ch * 16;
            cp16(d + P_A, Ahp + (row0 + r) * D_ + k0 + ch * 8);
            cp16(d + P_B, Bp + (col0 + r) * D_ + k0 + ch * 8);
        }
        CP_COMMIT();
    };

    issue(0, 0);
    issue(32, 1);

    const uint32_t aRow = lane & 15, aChk = lane >> 4;
    const uint32_t bRow = lane & 7,  bChk = (lane >> 3) & 1;

    for (int it = 0; it < NK_; ++it) {
        if (it + 1 < NK_) asm volatile("cp.async.wait_group 1;" ::: "memory");
        else              asm volatile("cp.async.wait_group 0;" ::: "memory");
        __syncthreads();
        if (it + 2 < NK_) issue((it + 2) * 32, (it + 2) % 3);

        const uint32_t st = sb + (it % 3) * STG1;
        const uint32_t sA = st + P_A + (wm * 64) * ROWB;
        const uint32_t sB = st + P_B + (wn * 64) * ROWB;

#pragma unroll
        for (int ks = 0; ks < 2; ++ks) {
            uint32_t ah[4][4], bb[8][2];
#pragma unroll
            for (int m = 0; m < 4; ++m) {
                const uint32_t ad = sA + (m * 16 + aRow) * ROWB + (ks * 2 + aChk) * 16;
                LDSM4(ah[m][0], ah[m][1], ah[m][2], ah[m][3], ad);
            }
#pragma unroll
            for (int n = 0; n < 8; ++n) {
                const uint32_t bd = sB + (n * 8 + bRow) * ROWB + (ks * 2 + bChk) * 16;
                LDSM2(bb[n][0], bb[n][1], bd);
            }
#pragma unroll
            for (int m = 0; m < 4; ++m)
#pragma unroll
                for (int n = 0; n < 8; ++n)
                    mma16816(acc[m][n], ah[m], bb[n]);
        }
    }

#pragma unroll
    for (int m = 0; m < 4; ++m) {
        const int r = (int)row0 + wm * 64 + m * 16 + (lane >> 2);
#pragma unroll
        for (int n = 0; n < 8; ++n) {
            const int cg = (int)col0 + wn * 64 + n * 8 + (lane & 3) * 2;
            *(float2*)(C + (size_t)r * N + cg) =
                make_float2(acc[m][n][0], acc[m][n][1]);
            *(float2*)(C + (size_t)(r + 8) * N + cg) =
                make_float2(acc[m][n][2], acc[m][n][3]);
        }
    }
}

// ---------------- rope ----------------
__global__ void rope_table()
{
    int i = blockIdx.x * 256 + threadIdx.x;
    int t = i >> 6, hf = i & 63;
    double invf = exp(-(double)hf * (9.210340371976184 / 64.0));
    double ph = (double)t * invf;
    g_trig[i] = make_float2((float)cos(ph), (float)sin(ph));
}

__global__ void rope_apply(float* __restrict__ X, int nheads, int total)
{
    int idx = blockIdx.x * 256 + threadIdx.x;
    if (idx >= total) return;
    int half = idx & 63;
    int head = (idx >> 6) % nheads;
    int row = idx / (64 * nheads);
    int t = row & (T_ - 1);
    float2 cs = g_trig[(t << 6) + half];
    size_t base = (size_t)row * nheads * HD_ + (size_t)head * HD_;
    float x1 = X[base + half], x2 = X[base + half + 64];
    X[base + half] = x1 * cs.x - x2 * cs.y;
    X[base + half + 64] = x2 * cs.x + x1 * cs.y;
}

// ---------------- HMMA flash attention (online max, softcap) -------------
__global__ __launch_bounds__(256) void attn_mma()
{
    extern __shared__ char smraw[];
    const uint32_t sb = smem_u32(smraw);
    const int tid = threadIdx.x, w = tid >> 5, lane = tid & 31;
    const int qt = blockIdx.x, h = blockIdx.y, b = blockIdx.z;
    const int kv = h / GRP_;
    const int g = lane >> 2, c2 = (lane & 3) * 2;
    const int rowbase = qt * 128 + w * 16;

    uint32_t qh[8][4], ql[8][4];
#pragma unroll
    for (int ks = 0; ks < 8; ++ks)
#pragma unroll
        for (int j = 0; j < 4; ++j) { qh[ks][j] = 0u; ql[ks][j] = 0u; }
#pragma unroll 1
    for (int half = 0; half < 2; ++half) {
        const float* Qg = g_Q + ((size_t)(b * T_) + qt * 128 + half * 64) * D_ + h * HD_;
        for (int i = tid; i < 2048; i += 256) {
            int r = i >> 5, ch = i & 31;
            cp16(sb + r * 512 + ch * 16, (const char*)(Qg + (size_t)r * D_) + ch * 16);
        }
        CP_COMMIT();
        asm volatile("cp.async.wait_group 0;" ::: "memory");
        __syncthreads();
        if ((w >> 2) == half) {
            int wr = (w & 3) * 16;
#pragma unroll
            for (int ks = 0; ks < 8; ++ks)
#pragma unroll
                for (int j = 0; j < 4; ++j) {
                    int row = wr + g + (j & 1) * 8;
                    int col = ks * 16 + (j >> 1) * 8 + c2;
                    float2 v = *(float2*)(smraw + row * 512 + col * 4);
                    __half hx = __float2half_rn(v.x), hy = __float2half_rn(v.y);
                    __half lx = __float2half_rn(v.x - __half2float(hx));
                    __half ly = __float2half_rn(v.y - __half2float(hy));
                    qh[ks][j] = (uint32_t)__half_as_ushort(hx) |
                                ((uint32_t)__half_as_ushort(hy) << 16);
                    ql[ks][j] = (uint32_t)__half_as_ushort(lx) |
                                ((uint32_t)__half_as_ushort(ly) << 16);
                }
        }
        __syncthreads();
    }

    float acc[17][4];
#pragma unroll
    for (int n = 0; n < 17; ++n)
#pragma unroll
        for (int i = 0; i < 4; ++i) acc[n][i] = 0.f;
    float m0 = -1e30f, m1 = -1e30f;

    const int ktmax = 4 * qt + 3;
    const int rowmax = rowbase + 15;
    const char* khg = (const char*)g_Kh + ((size_t)(b * NKV_ + kv) * T_) * HD_ * 2;
    const char* klg = (const char*)g_Kl + ((size_t)(b * NKV_ + kv) * T_) * HD_ * 2;
    const char* vtg = (const char*)g_VT + ((size_t)(b * NKV_ + kv) * 136) * T_ * 2;

    auto issueKV = [&](int kt) {
        const uint32_t sst = sb + (kt & 1) * AT_STG;
        const char* kh = khg + (size_t)kt * 32 * 256;
        const char* kl = klg + (size_t)kt * 32 * 256;
        const char* vt = vtg + (size_t)kt * 64;
        for (int i = tid; i < 1568; i += 256) {
            if (i < 512) {
                int r = i >> 4, ch = i & 15;
                cp16(sst + AT_KH + r * 272 + ch * 16, kh + r * 256 + ch * 16);
            } else if (i < 1024) {
                int j = i - 512, r = j >> 4, ch = j & 15;
                cp16(sst + AT_KL + r * 272 + ch * 16, kl + r * 256 + ch * 16);
            } else {
                int j = i - 1024, r = j >> 2, ch = j & 3;
                cp16(sst + AT_VT + r * 80 + ch * 16, vt + (size_t)r * 2048 + ch * 16);
            }
        }
        CP_COMMIT();
    };

    issueKV(0);
    for (int kt = 0; kt <= ktmax; ++kt) {
        if (kt < ktmax) {
            issueKV(kt + 1);
            asm volatile("cp.async.wait_group 1;" ::: "memory");
        } else {
            asm volatile("cp.async.wait_group 0;" ::: "memory");
        }
        __syncthreads();
        if (kt * 32 <= rowmax) {
            const uint32_t sst = sb + (kt & 1) * AT_STG;
            float lg[4][4];
#pragma unroll
            for (int nt = 0; nt < 4; ++nt) {
                float sacc[4] = {0.f, 0.f, 0.f, 0.f};
                const uint32_t ba0 = sst + (nt * 8 + (lane & 7)) * 272 +
                                     ((lane >> 3) & 1) * 16;
#pragma unroll
                for (int ks = 0; ks < 8; ++ks) {
                    uint32_t bh[2], bl[2];
                    LDSM2(bh[0], bh[1], ba0 + AT_KH + ks * 32);
                    LDSM2(bl[0], bl[1], ba0 + AT_KL + ks * 32);
                    mma16816(sacc, qh[ks], bh);
                    mma16816(sacc, ql[ks], bh);
                    mma16816(sacc, qh[ks], bl);
                }
                const int colb = kt * 32 + nt * 8 + c2;
#pragma unroll
                for (int i = 0; i < 4; ++i) {
                    int row = rowbase + g + (i >> 1) * 8;
                    int col = colb + (i & 1);
                    float u = ex2f(sacc[i] * CK_);
                    float r_ = rcpf(u + 1.0f);
                    lg[nt][i] = (col <= row) ? fmaf(-60.0f, r_, 30.0f) : -1e30f;
                }
            }
            float mx0 = fmaxf(fmaxf(fmaxf(lg[0][0], lg[0][1]), fmaxf(lg[1][0], lg[1][1])),
                              fmaxf(fmaxf(lg[2][0], lg[2][1]), fmaxf(lg[3][0], lg[3][1])));
            float mx1 = fmaxf(fmaxf(fmaxf(lg[0][2], lg[0][3]), fmaxf(lg[1][2], lg[1][3])),
                              fmaxf(fmaxf(lg[2][2], lg[2][3]), fmaxf(lg[3][2], lg[3][3])));
            mx0 = fmaxf(mx0, __shfl_xor_sync(0xffffffffu, mx0, 1));
            mx0 = fmaxf(mx0, __shfl_xor_sync(0xffffffffu, mx0, 2));
            mx1 = fmaxf(mx1, __shfl_xor_sync(0xffffffffu, mx1, 1));
            mx1 = fmaxf(mx1, __shfl_xor_sync(0xffffffffu, mx1, 2));
            float nm0 = fmaxf(m0, mx0), nm1 = fmaxf(m1, mx1);
            float s0 = ex2f((m0 - nm0) * L2E_);
            float s1 = ex2f((m1 - nm1) * L2E_);
            m0 = nm0; m1 = nm1;
#pragma unroll
            for (int n = 0; n < 17; ++n) {
                acc[n][0] *= s0; acc[n][1] *= s0;
                acc[n][2] *= s1; acc[n][3] *= s1;
            }
            uint32_t pf[4][2];
#pragma unroll
            for (int nt = 0; nt < 4; ++nt) {
                float p0 = ex2f((lg[nt][0] - m0) * L2E_);
                float p1 = ex2f((lg[nt][1] - m0) * L2E_);
                float p2 = ex2f((lg[nt][2] - m1) * L2E_);
                float p3 = ex2f((lg[nt][3] - m1) * L2E_);
                pf[nt][0] = packh2(p0, p1);
                pf[nt][1] = packh2(p2, p3);
            }
#pragma unroll
            for (int kp = 0; kp < 2; ++kp) {
                uint32_t a[4] = {pf[2 * kp][0], pf[2 * kp][1],
                                 pf[2 * kp + 1][0], pf[2 * kp + 1][1]};
                const uint32_t vb0 = sst + AT_VT + (lane & 7) * 80 +
                                     (kp * 2 + ((lane >> 3) & 1)) * 16;
#pragma unroll
                for (int n = 0; n < 17; ++n) {
                    uint32_t bv[2];
                    LDSM2(bv[0], bv[1], vb0 + n * 8 * 80);
                    mma16816(acc[n], a, bv);
                }
            }
        }
        __syncthreads();
    }

    // ---- epilogue: normalize, fp16 hi only (O-proj is single-stream) ----
    float l0 = __shfl_sync(0xffffffffu, acc[16][0], lane & 28);
    float l1 = __shfl_sync(0xffffffffu, acc[16][2], lane & 28);
    float i0 = __fdividef(1.0f, l0);
    float i1 = __fdividef(1.0f, l1);
    const size_t r0 = (size_t)(b * T_ + rowbase + g) * D_ + h * HD_ + c2;
    const size_t r1 = r0 + (size_t)8 * D_;
#pragma unroll
    for (int nt = 0; nt < 16; ++nt) {
        *(uint32_t*)(g_Ah + r0 + nt * 8) = packh2(acc[nt][0] * i0, acc[nt][1] * i0);
        *(uint32_t*)(g_Ah + r1 + nt * 8) = packh2(acc[nt][2] * i1, acc[nt][3] * i1);
    }
}

// ---------------- launch ----------------
extern "C" void kernel_launch(void* const* d_in, const int* in_sizes, int n_in,
                              void* d_out, int out_size)
{
    (void)in_sizes; (void)n_in; (void)out_size;
    const float* query = (const float*)d_in[0];
    const float* key   = (const float*)d_in[1];
    const float* value = (const float*)d_in[2];
    const float* wq = (const float*)d_in[4];
    const float* bq = (const float*)d_in[5];
    const float* wk = (const float*)d_in[6];
    const float* bk = (const float*)d_in[7];
    const float* wv = (const float*)d_in[8];
    const float* bv = (const float*)d_in[9];
    const float* wo = (const float*)d_in[10];
    float* out = (float*)d_out;

    cudaFuncSetAttribute(gemm_qkv, cudaFuncAttributeMaxDynamicSharedMemorySize, SMEM_TOT);
    cudaFuncSetAttribute(gemm_o,  cudaFuncAttributeMaxDynamicSharedMemorySize, SMEM_O);
    cudaFuncSetAttribute(attn_mma, cudaFuncAttributeMaxDynamicSharedMemorySize, AT_SMEM);

    float *Qp, *Kp, *Vp;
    __half *Ah, *Wq, *Wk, *Wv, *Wo;
    cudaGetSymbolAddress((void**)&Qp, g_Q);
    cudaGetSymbolAddress((void**)&Kp, g_K);
    cudaGetSymbolAddress((void**)&Vp, g_V);
    cudaGetSymbolAddress((void**)&Ah, g_Ah);
    cudaGetSymbolAddress((void**)&Wq, g_Wq);
    cudaGetSymbolAddress((void**)&Wk, g_Wk);
    cudaGetSymbolAddress((void**)&Wv, g_Wv);
    cudaGetSymbolAddress((void**)&Wo, g_Wo);

    const int M = B_ * T_;
    const int n4 = M * D_ / 4;

    wT_fp16<<<dim3(D_ / 32, D_ / 32), dim3(32, 8)>>>(wq, Wq, D_, D_);
    wT_fp16<<<dim3(KVD_ / 32, D_ / 32), dim3(32, 8)>>>(wk, Wk, D_, KVD_);
    wT_fp16<<<dim3(KVD_ / 32, D_ / 32), dim3(32, 8)>>>(wv, Wv, D_, KVD_);
    wT_fp16<<<dim3(D_ / 32, D_ / 32), dim3(32, 8)>>>(wo, Wo, D_, D_);
    rope_table<<<256, 256>>>();

    // fused splits
    split3<<<(3 * n4 + 255) / 256, 256>>>(query, key, value, n4);

    // fused Q+K+V projection
    gemm_qkv<<<1024, 128, SMEM_TOT>>>(bq, bk, bv);

    // rope
    rope_apply<<<(M * NQ_ * 64 + 255) / 256, 256>>>(Qp, NQ_, M * NQ_ * 64);
    rope_apply<<<(M * NKV_ * 64 + 255) / 256, 256>>>(Kp, NKV_, M * NKV_ * 64);

    // attention prep
    kvsplit<<<(B_ * NKV_ * T_ * 32) / 256, 256>>>(Kp);
    vtsplit<<<(16 * 136 * 256 + 255) / 256, 256>>>(Vp);

    // flash attention -> writes g_Ah (hi only)
    attn_mma<<<dim3(T_ / 128, NQ_, B_), 256, AT_SMEM>>>();

    // output projection (single stream)
    gemm_o<<<dim3(M / 128, D_ / 128), 128, SMEM_O>>>(Ah, Wo, out, D_);
}

// round 15
// speedup vs baseline: 1.3700x; 1.0021x over previous
#include <cuda_runtime.h>
#include <cuda_fp16.h>
#include <stdint.h>
#include <math.h>

#define B_   2
#define T_   1024
#define D_   6144
#define NQ_  48
#define NKV_ 8
#define HD_  128
#define GRP_ 6
#define KVD_ 1024
#define MULT_ 0.08838834764831845f
#define CK_  0.0085011611f
#define L2E_ 1.4426950408889634f

#define NK_   (D_ / 32)
#define ROWB  80
/* 2-stream (QKV) gemm smem */
#define O_AH  0
#define O_AL  10240
#define O_B   20480
#define STG   30720
#define SMEM_TOT (3 * STG)
/* 1-stream (O-proj) gemm smem */
#define P_A   0
#define P_B   10240
#define STG1  20480
#define SMEM_O (3 * STG1)

#define AT_KH 0
#define AT_KL 8704
#define AT_VT 17408
#define AT_STG 28288
#define AT_SMEM (2 * AT_STG)

// ---------------- scratch ----------------
__device__ __align__(128) float g_Q[(size_t)B_ * T_ * D_];
__device__ __align__(128) float g_K[(size_t)B_ * T_ * KVD_];
__device__ __align__(128) float g_V[(size_t)B_ * T_ * KVD_];
__device__ __align__(16) __half g_Ah[(size_t)B_ * T_ * D_];
__device__ __align__(16) __half g_Al[(size_t)B_ * T_ * D_];
__device__ __align__(16) __half g_KAh[(size_t)B_ * T_ * D_];
__device__ __align__(16) __half g_KAl[(size_t)B_ * T_ * D_];
__device__ __align__(16) __half g_VAh[(size_t)B_ * T_ * D_];
__device__ __align__(16) __half g_VAl[(size_t)B_ * T_ * D_];
__device__ __align__(16) __half g_Kh[(size_t)B_ * NKV_ * T_ * HD_];
__device__ __align__(16) __half g_Kl[(size_t)B_ * NKV_ * T_ * HD_];
__device__ __align__(16) __half g_VT[(size_t)B_ * NKV_ * 136 * T_];
__device__ __align__(16) __half g_Wq[(size_t)D_ * D_];
__device__ __align__(16) __half g_Wk[(size_t)KVD_ * D_];
__device__ __align__(16) __half g_Wv[(size_t)KVD_ * D_];
__device__ __align__(16) __half g_Wo[(size_t)D_ * D_];
__device__ float2 g_trig[T_ * 64];

// ---------------- ptx helpers ----------------
__device__ __forceinline__ uint32_t smem_u32(const void* p) {
    uint32_t a;
    asm("{ .reg .u64 t; cvta.to.shared.u64 t, %1; cvt.u32.u64 %0, t; }" : "=r"(a) : "l"(p));
    return a;
}
__device__ __forceinline__ void cp16(uint32_t d, const void* s) {
    asm volatile("cp.async.cg.shared.global [%0], [%1], 16;" :: "r"(d), "l"(s));
}
#define CP_COMMIT() asm volatile("cp.async.commit_group;" ::: "memory")
#define LDSM4(r0, r1, r2, r3, a) \
    asm volatile("ldmatrix.sync.aligned.m8n8.x4.shared.b16 {%0,%1,%2,%3}, [%4];" \
                 : "=r"(r0), "=r"(r1), "=r"(r2), "=r"(r3) : "r"(a))
#define LDSM2(r0, r1, a) \
    asm volatile("ldmatrix.sync.aligned.m8n8.x2.shared.b16 {%0,%1}, [%2];" \
                 : "=r"(r0), "=r"(r1) : "r"(a))
__device__ __forceinline__ void mma16816(float* c, const uint32_t* a, const uint32_t* b) {
    asm volatile(
        "mma.sync.aligned.m16n8k16.row.col.f32.f16.f16.f32 "
        "{%0,%1,%2,%3}, {%4,%5,%6,%7}, {%8,%9}, {%0,%1,%2,%3};"
        : "+f"(c[0]), "+f"(c[1]), "+f"(c[2]), "+f"(c[3])
        : "r"(a[0]), "r"(a[1]), "r"(a[2]), "r"(a[3]), "r"(b[0]), "r"(b[1]));
}
__device__ __forceinline__ uint32_t packh2(float x, float y) {
    __half2 h = __floats2half2_rn(x, y);
    return *(uint32_t*)&h;
}
__device__ __forceinline__ float ex2f(float x) {
    float r; asm("ex2.approx.f32 %0, %1;" : "=f"(r) : "f"(x)); return r;
}
__device__ __forceinline__ float rcpf(float x) {
    float r; asm("rcp.approx.f32 %0, %1;" : "=f"(r) : "f"(x)); return r;
}

// ---------------- prep kernels ----------------
__global__ __launch_bounds__(256) void wT_fp16(
    const float* __restrict__ W, __half* __restrict__ Tr, int K, int N)
{
    __shared__ float tb[32][33];
    const int n0 = blockIdx.x * 32, k0 = blockIdx.y * 32;
    const int tx = threadIdx.x, ty = threadIdx.y;
#pragma unroll
    for (int j = 0; j < 4; ++j)
        tb[ty + j * 8][tx] = W[(size_t)(k0 + ty + j * 8) * N + n0 + tx];
    __syncthreads();
#pragma unroll
    for (int j = 0; j < 4; ++j) {
        int n = ty + j * 8;
        Tr[(size_t)(n0 + n) * K + k0 + tx] = __float2half_rn(tb[tx][n]);
    }
}

// fused 3-way fp32 -> fp16 hi/lo split (query/key/value)
__global__ __launch_bounds__(256) void split3(
    const float* __restrict__ q, const float* __restrict__ k,
    const float* __restrict__ v, int n4)
{
    int i = blockIdx.x * 256 + threadIdx.x;
    if (i >= 3 * n4) return;
    const float* X;
    __half *H, *L;
    if (i < n4)          { X = q; H = g_Ah;  L = g_Al;  }
    else if (i < 2 * n4) { X = k; H = g_KAh; L = g_KAl; i -= n4; }
    else                 { X = v; H = g_VAh; L = g_VAl; i -= 2 * n4; }
    float4 val = ((const float4*)X)[i];
    ushort4 hh, ll;
    float f[4] = {val.x, val.y, val.z, val.w};
    unsigned short* hp = &hh.x; unsigned short* lp = &ll.x;
#pragma unroll
    for (int j = 0; j < 4; ++j) {
        __half h = __float2half_rn(f[j]);
        __half l = __float2half_rn(f[j] - __half2float(h));
        hp[j] = __half_as_ushort(h); lp[j] = __half_as_ushort(l);
    }
    ((ushort4*)H)[i] = hh; ((ushort4*)L)[i] = ll;
}

__global__ __launch_bounds__(256) void kvsplit(const float* __restrict__ K)
{
    int i = blockIdx.x * 256 + threadIdx.x;
    int d4 = i & 31, t = (i >> 5) & (T_ - 1), kvb = i >> 15;
    int b = kvb >> 3, kv = kvb & 7;
    float4 v = *(const float4*)(K + ((size_t)(b * T_ + t) * KVD_ + kv * 128 + d4 * 4));
    ushort4 hh, ll;
    float f[4] = {v.x, v.y, v.z, v.w};
    unsigned short* hp = &hh.x; unsigned short* lp = &ll.x;
#pragma unroll
    for (int k = 0; k < 4; ++k) {
        __half h = __float2half_rn(f[k]);
        __half l = __float2half_rn(f[k] - __half2float(h));
        hp[k] = __half_as_ushort(h); lp[k] = __half_as_ushort(l);
    }
    size_t o = ((size_t)kvb * T_ + t) * 128 + d4 * 4;
    *(ushort4*)(g_Kh + o) = hh; *(ushort4*)(g_Kl + o) = ll;
}

__global__ __launch_bounds__(256) void vtsplit(const float* __restrict__ V)
{
    int i = blockIdx.x * 256 + threadIdx.x;
    if (i >= 16 * 136 * 256) return;
    int t4 = i & 255, n = (i >> 8) % 136, kvb = i / (136 * 256);
    int b = kvb >> 3, kv = kvb & 7;
    ushort4 o;
    unsigned short* op = &o.x;
    int t = t4 * 4;
#pragma unroll
    for (int j = 0; j < 4; ++j) {
        float x = (n < 128) ? V[(size_t)(b * T_ + t + j) * KVD_ + kv * 128 + n]
                            : (n == 128 ? 1.0f : 0.0f);
        op[j] = __half_as_ushort(__float2half_rn(x));
    }
    *(ushort4*)(g_VT + ((size_t)kvb * 136 + n) * T_ + t) = o;
}

// ---------------- 2-stream GEMM body (QKV projections) ----------------
__device__ __forceinline__ void gemm_body(
    const __half* __restrict__ Ahp, const __half* __restrict__ Alp,
    const __half* __restrict__ Bp,
    const float* __restrict__ bias, float* __restrict__ C, int N,
    int bx, int by, char* smraw)
{
    const uint32_t sb = smem_u32(smraw);
    const int tid = threadIdx.x, wid = tid >> 5, lane = tid & 31;
    const int wm = wid & 1, wn = wid >> 1;
    const size_t row0 = (size_t)bx * 128;
    const size_t col0 = (size_t)by * 128;

    float acc[4][8][4];
#pragma unroll
    for (int m = 0; m < 4; ++m)
#pragma unroll
        for (int n = 0; n < 8; ++n)
#pragma unroll
            for (int i = 0; i < 4; ++i) acc[m][n][i] = 0.f;

    auto issue = [&](int k0, int stg) {
        const uint32_t sbase = sb + stg * STG;
#pragma unroll
        for (int i = tid; i < 512; i += 128) {
            const int r = i >> 2, ch = i & 3;
            const size_t gA = (row0 + r) * D_ + k0 + ch * 8;
            const uint32_t d = sbase + r * ROWB + ch * 16;
            cp16(d + O_AH, Ahp + gA);
            cp16(d + O_AL, Alp + gA);
            cp16(d + O_B,  Bp + (col0 + r) * D_ + k0 + ch * 8);
        }
        CP_COMMIT();
    };

    issue(0, 0);
    issue(32, 1);

    const uint32_t aRow = lane & 15, aChk = lane >> 4;
    const uint32_t bRow = lane & 7,  bChk = (lane >> 3) & 1;

    for (int it = 0; it < NK_; ++it) {
        if (it + 1 < NK_) asm volatile("cp.async.wait_group 1;" ::: "memory");
        else              asm volatile("cp.async.wait_group 0;" ::: "memory");
        __syncthreads();
        if (it + 2 < NK_) issue((it + 2) * 32, (it + 2) % 3);

        const uint32_t st = sb + (it % 3) * STG;
        const uint32_t sA = st + (wm * 64) * ROWB;
        const uint32_t sB = st + O_B + (wn * 64) * ROWB;

#pragma unroll
        for (int ks = 0; ks < 2; ++ks) {
            uint32_t ah[4][4], al[4][4], bb[8][2];
#pragma unroll
            for (int m = 0; m < 4; ++m) {
                const uint32_t ad = sA + (m * 16 + aRow) * ROWB + (ks * 2 + aChk) * 16;
                LDSM4(ah[m][0], ah[m][1], ah[m][2], ah[m][3], ad + O_AH);
                LDSM4(al[m][0], al[m][1], al[m][2], al[m][3], ad + O_AL);
            }
#pragma unroll
            for (int n = 0; n < 8; ++n) {
                const uint32_t bd = sB + (n * 8 + bRow) * ROWB + (ks * 2 + bChk) * 16;
                LDSM2(bb[n][0], bb[n][1], bd);
            }
#pragma unroll
            for (int m = 0; m < 4; ++m)
#pragma unroll
                for (int n = 0; n < 8; ++n) {
                    mma16816(acc[m][n], ah[m], bb[n]);
                    mma16816(acc[m][n], al[m], bb[n]);
                }
        }
    }

#pragma unroll
    for (int m = 0; m < 4; ++m) {
        const int r = (int)row0 + wm * 64 + m * 16 + (lane >> 2);
#pragma unroll
        for (int n = 0; n < 8; ++n) {
            const int cg = (int)col0 + wn * 64 + n * 8 + (lane & 3) * 2;
            float b0 = bias ? bias[cg] : 0.f, b1 = bias ? bias[cg + 1] : 0.f;
            float2 v0 = make_float2(acc[m][n][0] + b0, acc[m][n][1] + b1);
            float2 v1 = make_float2(acc[m][n][2] + b0, acc[m][n][3] + b1);
            *(float2*)(C + (size_t)r * N + cg) = v0;
            *(float2*)(C + (size_t)(r + 8) * N + cg) = v1;
        }
    }
}

// Fused Q+K+V projections: 1024 CTAs
__global__ __launch_bounds__(128, 2) void gemm_qkv(
    const float* __restrict__ bq, const float* __restrict__ bk,
    const float* __restrict__ bv)
{
    extern __shared__ char smraw[];
    const int id = blockIdx.x;
    const __half *Ah, *Al, *Bw;
    const float* bias;
    float* C;
    int N, bx, by;
    if (id < 768) {
        Ah = g_Ah;  Al = g_Al;  Bw = g_Wq; bias = bq; C = g_Q; N = D_;
        bx = id & 15; by = id >> 4;
    } else if (id < 896) {
        int j = id - 768;
        Ah = g_KAh; Al = g_KAl; Bw = g_Wk; bias = bk; C = g_K; N = KVD_;
        bx = j & 15; by = j >> 4;
    } else {
        int j = id - 896;
        Ah = g_VAh; Al = g_VAl; Bw = g_Wv; bias = bv; C = g_V; N = KVD_;
        bx = j & 15; by = j >> 4;
    }
    gemm_body(Ah, Al, Bw, bias, C, N, bx, by, smraw);
}

// ---------------- 1-stream GEMM (O projection) ----------------
__global__ __launch_bounds__(128, 2) void gemm_o(
    const __half* __restrict__ Ahp, const __half* __restrict__ Bp,
    float* __restrict__ C, int N)
{
    extern __shared__ char smraw[];
    const uint32_t sb = smem_u32(smraw);
    const int tid = threadIdx.x, wid = tid >> 5, lane = tid & 31;
    const int wm = wid & 1, wn = wid >> 1;
    const size_t row0 = (size_t)blockIdx.x * 128;
    const size_t col0 = (size_t)blockIdx.y * 128;

    float acc[4][8][4];
#pragma unroll
    for (int m = 0; m < 4; ++m)
#pragma unroll
        for (int n = 0; n < 8; ++n)
#pragma unroll
            for (int i = 0; i < 4; ++i) acc[m][n][i] = 0.f;

    auto issue = [&](int k0, int stg) {
        const uint32_t sbase = sb + stg * STG1;
#pragma unroll
        for (int i = tid; i < 512; i += 128) {
            const int r = i >> 2, ch = i & 3;
            const uint32_t d = sbase + r * ROWB + ch * 16;
            cp16(d + P_A, Ahp + (row0 + r) * D_ + k0 + ch * 8);
            cp16(d + P_B, Bp + (col0 + r) * D_ + k0 + ch * 8);
        }
        CP_COMMIT();
    };

    issue(0, 0);
    issue(32, 1);

    const uint32_t aRow = lane & 15, aChk = lane >> 4;
    const uint32_t bRow = lane & 7,  bChk = (lane >> 3) & 1;

    for (int it = 0; it < NK_; ++it) {
        if (it + 1 < NK_) asm volatile("cp.async.wait_group 1;" ::: "memory");
        else              asm volatile("cp.async.wait_group 0;" ::: "memory");
        __syncthreads();
        if (it + 2 < NK_) issue((it + 2) * 32, (it + 2) % 3);

        const uint32_t st = sb + (it % 3) * STG1;
        const uint32_t sA = st + P_A + (wm * 64) * ROWB;
        const uint32_t sB = st + P_B + (wn * 64) * ROWB;

#pragma unroll
        for (int ks = 0; ks < 2; ++ks) {
            uint32_t ah[4][4], bb[8][2];
#pragma unroll
            for (int m = 0; m < 4; ++m) {
                const uint32_t ad = sA + (m * 16 + aRow) * ROWB + (ks * 2 + aChk) * 16;
                LDSM4(ah[m][0], ah[m][1], ah[m][2], ah[m][3], ad);
            }
#pragma unroll
            for (int n = 0; n < 8; ++n) {
                const uint32_t bd = sB + (n * 8 + bRow) * ROWB + (ks * 2 + bChk) * 16;
                LDSM2(bb[n][0], bb[n][1], bd);
            }
#pragma unroll
            for (int m = 0; m < 4; ++m)
#pragma unroll
                for (int n = 0; n < 8; ++n)
                    mma16816(acc[m][n], ah[m], bb[n]);
        }
    }

#pragma unroll
    for (int m = 0; m < 4; ++m) {
        const int r = (int)row0 + wm * 64 + m * 16 + (lane >> 2);
#pragma unroll
        for (int n = 0; n < 8; ++n) {
            const int cg = (int)col0 + wn * 64 + n * 8 + (lane & 3) * 2;
            *(float2*)(C + (size_t)r * N + cg) =
                make_float2(acc[m][n][0], acc[m][n][1]);
            *(float2*)(C + (size_t)(r + 8) * N + cg) =
                make_float2(acc[m][n][2], acc[m][n][3]);
        }
    }
}

// ---------------- rope ----------------
__global__ void rope_table()
{
    int i = blockIdx.x * 256 + threadIdx.x;
    int t = i >> 6, hf = i & 63;
    double invf = exp(-(double)hf * (9.210340371976184 / 64.0));
    double ph = (double)t * invf;
    g_trig[i] = make_float2((float)cos(ph), (float)sin(ph));
}

__global__ void rope_apply(float* __restrict__ X, int nheads, int total)
{
    int idx = blockIdx.x * 256 + threadIdx.x;
    if (idx >= total) return;
    int half = idx & 63;
    int head = (idx >> 6) % nheads;
    int row = idx / (64 * nheads);
    int t = row & (T_ - 1);
    float2 cs = g_trig[(t << 6) + half];
    size_t base = (size_t)row * nheads * HD_ + (size_t)head * HD_;
    float x1 = X[base + half], x2 = X[base + half + 64];
    X[base + half] = x1 * cs.x - x2 * cs.y;
    X[base + half + 64] = x2 * cs.x + x1 * cs.y;
}

// ---------------- HMMA flash attention (online max, softcap) -------------
__global__ __launch_bounds__(256) void attn_mma()
{
    extern __shared__ char smraw[];
    const uint32_t sb = smem_u32(smraw);
    const int tid = threadIdx.x, w = tid >> 5, lane = tid & 31;
    const int qt = blockIdx.x, h = blockIdx.y, b = blockIdx.z;
    const int kv = h / GRP_;
    const int g = lane >> 2, c2 = (lane & 3) * 2;
    const int rowbase = qt * 128 + w * 16;

    uint32_t qh[8][4], ql[8][4];
#pragma unroll
    for (int ks = 0; ks < 8; ++ks)
#pragma unroll
        for (int j = 0; j < 4; ++j) { qh[ks][j] = 0u; ql[ks][j] = 0u; }
#pragma unroll 1
    for (int half = 0; half < 2; ++half) {
        const float* Qg = g_Q + ((size_t)(b * T_) + qt * 128 + half * 64) * D_ + h * HD_;
        for (int i = tid; i < 2048; i += 256) {
            int r = i >> 5, ch = i & 31;
            cp16(sb + r * 512 + ch * 16, (const char*)(Qg + (size_t)r * D_) + ch * 16);
        }
        CP_COMMIT();
        asm volatile("cp.async.wait_group 0;" ::: "memory");
        __syncthreads();
        if ((w >> 2) == half) {
            int wr = (w & 3) * 16;
#pragma unroll
            for (int ks = 0; ks < 8; ++ks)
#pragma unroll
                for (int j = 0; j < 4; ++j) {
                    int row = wr + g + (j & 1) * 8;
                    int col = ks * 16 + (j >> 1) * 8 + c2;
                    float2 v = *(float2*)(smraw + row * 512 + col * 4);
                    __half hx = __float2half_rn(v.x), hy = __float2half_rn(v.y);
                    __half lx = __float2half_rn(v.x - __half2float(hx));
                    __half ly = __float2half_rn(v.y - __half2float(hy));
                    qh[ks][j] = (uint32_t)__half_as_ushort(hx) |
                                ((uint32_t)__half_as_ushort(hy) << 16);
                    ql[ks][j] = (uint32_t)__half_as_ushort(lx) |
                                ((uint32_t)__half_as_ushort(ly) << 16);
                }
        }
        __syncthreads();
    }

    float acc[17][4];
#pragma unroll
    for (int n = 0; n < 17; ++n)
#pragma unroll
        for (int i = 0; i < 4; ++i) acc[n][i] = 0.f;
    float m0 = -1e30f, m1 = -1e30f;

    const int ktmax = 4 * qt + 3;
    const int rowmax = rowbase + 15;
    const char* khg = (const char*)g_Kh + ((size_t)(b * NKV_ + kv) * T_) * HD_ * 2;
    const char* klg = (const char*)g_Kl + ((size_t)(b * NKV_ + kv) * T_) * HD_ * 2;
    const char* vtg = (const char*)g_VT + ((size_t)(b * NKV_ + kv) * 136) * T_ * 2;

    auto issueKV = [&](int kt) {
        const uint32_t sst = sb + (kt & 1) * AT_STG;
        const char* kh = khg + (size_t)kt * 32 * 256;
        const char* kl = klg + (size_t)kt * 32 * 256;
        const char* vt = vtg + (size_t)kt * 64;
        for (int i = tid; i < 1568; i += 256) {
            if (i < 512) {
                int r = i >> 4, ch = i & 15;
                cp16(sst + AT_KH + r * 272 + ch * 16, kh + r * 256 + ch * 16);
            } else if (i < 1024) {
                int j = i - 512, r = j >> 4, ch = j & 15;
                cp16(sst + AT_KL + r * 272 + ch * 16, kl + r * 256 + ch * 16);
            } else {
                int j = i - 1024, r = j >> 2, ch = j & 3;
                cp16(sst + AT_VT + r * 80 + ch * 16, vt + (size_t)r * 2048 + ch * 16);
            }
        }
        CP_COMMIT();
    };

    issueKV(0);
    for (int kt = 0; kt <= ktmax; ++kt) {
        if (kt < ktmax) {
            issueKV(kt + 1);
            asm volatile("cp.async.wait_group 1;" ::: "memory");
        } else {
            asm volatile("cp.async.wait_group 0;" ::: "memory");
        }
        __syncthreads();
        if (kt * 32 <= rowmax) {
            const uint32_t sst = sb + (kt & 1) * AT_STG;
            float lg[4][4];
#pragma unroll
            for (int nt = 0; nt < 4; ++nt) {
                float sacc[4] = {0.f, 0.f, 0.f, 0.f};
                const uint32_t ba0 = sst + (nt * 8 + (lane & 7)) * 272 +
                                     ((lane >> 3) & 1) * 16;
#pragma unroll
                for (int ks = 0; ks < 8; ++ks) {
                    uint32_t bh[2], bl[2];
                    LDSM2(bh[0], bh[1], ba0 + AT_KH + ks * 32);
                    LDSM2(bl[0], bl[1], ba0 + AT_KL + ks * 32);
                    mma16816(sacc, qh[ks], bh);
                    mma16816(sacc, ql[ks], bh);
                    mma16816(sacc, qh[ks], bl);
                }
                const int colb = kt * 32 + nt * 8 + c2;
#pragma unroll
                for (int i = 0; i < 4; ++i) {
                    int row = rowbase + g + (i >> 1) * 8;
                    int col = colb + (i & 1);
                    float u = ex2f(sacc[i] * CK_);
                    float r_ = rcpf(u + 1.0f);
                    lg[nt][i] = (col <= row) ? fmaf(-60.0f, r_, 30.0f) : -1e30f;
                }
            }
            float mx0 = fmaxf(fmaxf(fmaxf(lg[0][0], lg[0][1]), fmaxf(lg[1][0], lg[1][1])),
                              fmaxf(fmaxf(lg[2][0], lg[2][1]), fmaxf(lg[3][0], lg[3][1])));
            float mx1 = fmaxf(fmaxf(fmaxf(lg[0][2], lg[0][3]), fmaxf(lg[1][2], lg[1][3])),
                              fmaxf(fmaxf(lg[2][2], lg[2][3]), fmaxf(lg[3][2], lg[3][3])));
            mx0 = fmaxf(mx0, __shfl_xor_sync(0xffffffffu, mx0, 1));
            mx0 = fmaxf(mx0, __shfl_xor_sync(0xffffffffu, mx0, 2));
            mx1 = fmaxf(mx1, __shfl_xor_sync(0xffffffffu, mx1, 1));
            mx1 = fmaxf(mx1, __shfl_xor_sync(0xffffffffu, mx1, 2));
            float nm0 = fmaxf(m0, mx0), nm1 = fmaxf(m1, mx1);
            float s0 = ex2f((m0 - nm0) * L2E_);
            float s1 = ex2f((m1 - nm1) * L2E_);
            m0 = nm0; m1 = nm1;
#pragma unroll
            for (int n = 0; n < 17; ++n) {
                acc[n][0] *= s0; acc[n][1] *= s0;
                acc[n][2] *= s1; acc[n][3] *= s1;
            }
            uint32_t pf[4][2];
#pragma unroll
            for (int nt = 0; nt < 4; ++nt) {
                float p0 = ex2f((lg[nt][0] - m0) * L2E_);
                float p1 = ex2f((lg[nt][1] - m0) * L2E_);
                float p2 = ex2f((lg[nt][2] - m1) * L2E_);
                float p3 = ex2f((lg[nt][3] - m1) * L2E_);
                pf[nt][0] = packh2(p0, p1);
                pf[nt][1] = packh2(p2, p3);
            }
#pragma unroll
            for (int kp = 0; kp < 2; ++kp) {
                uint32_t a[4] = {pf[2 * kp][0], pf[2 * kp][1],
                                 pf[2 * kp + 1][0], pf[2 * kp + 1][1]};
                const uint32_t vb0 = sst + AT_VT + (lane & 7) * 80 +
                                     (kp * 2 + ((lane >> 3) & 1)) * 16;
#pragma unroll
                for (int n = 0; n < 17; ++n) {
                    uint32_t bv[2];
                    LDSM2(bv[0], bv[1], vb0 + n * 8 * 80);
                    mma16816(acc[n], a, bv);
                }
            }
        }
        __syncthreads();
    }

    // ---- epilogue: normalize, fp16 hi only (O-proj is single-stream) ----
    float l0 = __shfl_sync(0xffffffffu, acc[16][0], lane & 28);
    float l1 = __shfl_sync(0xffffffffu, acc[16][2], lane & 28);
    float i0 = __fdividef(1.0f, l0);
    float i1 = __fdividef(1.0f, l1);
    const size_t r0 = (size_t)(b * T_ + rowbase + g) * D_ + h * HD_ + c2;
    const size_t r1 = r0 + (size_t)8 * D_;
#pragma unroll
    for (int nt = 0; nt < 16; ++nt) {
        *(uint32_t*)(g_Ah + r0 + nt * 8) = packh2(acc[nt][0] * i0, acc[nt][1] * i0);
        *(uint32_t*)(g_Ah + r1 + nt * 8) = packh2(acc[nt][2] * i1, acc[nt][3] * i1);
    }
}

// ---------------- launch ----------------
extern "C" void kernel_launch(void* const* d_in, const int* in_sizes, int n_in,
                              void* d_out, int out_size)
{
    (void)in_sizes; (void)n_in; (void)out_size;
    const float* query = (const float*)d_in[0];
    const float* key   = (const float*)d_in[1];
    const float* value = (const float*)d_in[2];
    const float* wq = (const float*)d_in[4];
    const float* bq = (const float*)d_in[5];
    const float* wk = (const float*)d_in[6];
    const float* bk = (const float*)d_in[7];
    const float* wv = (const float*)d_in[8];
    const float* bv = (const float*)d_in[9];
    const float* wo = (const float*)d_in[10];
    float* out = (float*)d_out;

    cudaFuncSetAttribute(gemm_qkv, cudaFuncAttributeMaxDynamicSharedMemorySize, SMEM_TOT);
    cudaFuncSetAttribute(gemm_o,  cudaFuncAttributeMaxDynamicSharedMemorySize, SMEM_O);
    cudaFuncSetAttribute(attn_mma, cudaFuncAttributeMaxDynamicSharedMemorySize, AT_SMEM);

    float *Qp, *Kp, *Vp;
    __half *Ah, *Wq, *Wk, *Wv, *Wo;
    cudaGetSymbolAddress((void**)&Qp, g_Q);
    cudaGetSymbolAddress((void**)&Kp, g_K);
    cudaGetSymbolAddress((void**)&Vp, g_V);
    cudaGetSymbolAddress((void**)&Ah, g_Ah);
    cudaGetSymbolAddress((void**)&Wq, g_Wq);
    cudaGetSymbolAddress((void**)&Wk, g_Wk);
    cudaGetSymbolAddress((void**)&Wv, g_Wv);
    cudaGetSymbolAddress((void**)&Wo, g_Wo);

    const int M = B_ * T_;
    const int n4 = M * D_ / 4;

    wT_fp16<<<dim3(D_ / 32, D_ / 32), dim3(32, 8)>>>(wq, Wq, D_, D_);
    wT_fp16<<<dim3(KVD_ / 32, D_ / 32), dim3(32, 8)>>>(wk, Wk, D_, KVD_);
    wT_fp16<<<dim3(KVD_ / 32, D_ / 32), dim3(32, 8)>>>(wv, Wv, D_, KVD_);
    wT_fp16<<<dim3(D_ / 32, D_ / 32), dim3(32, 8)>>>(wo, Wo, D_, D_);
    rope_table<<<256, 256>>>();

    // fused splits
    split3<<<(3 * n4 + 255) / 256, 256>>>(query, key, value, n4);

    // fused Q+K+V projection
    gemm_qkv<<<1024, 128, SMEM_TOT>>>(bq, bk, bv);

    // rope
    rope_apply<<<(M * NQ_ * 64 + 255) / 256, 256>>>(Qp, NQ_, M * NQ_ * 64);
    rope_apply<<<(M * NKV_ * 64 + 255) / 256, 256>>>(Kp, NKV_, M * NKV_ * 64);

    // attention prep
    kvsplit<<<(B_ * NKV_ * T_ * 32) / 256, 256>>>(Kp);
    vtsplit<<<(16 * 136 * 256 + 255) / 256, 256>>>(Vp);

    // flash attention -> writes g_Ah (hi only)
    attn_mma<<<dim3(T_ / 128, NQ_, B_), 256, AT_SMEM>>>();

    // output projection (single stream)
    gemm_o<<<dim3(M / 128, D_ / 128), 128, SMEM_O>>>(Ah, Wo, out, D_);
}